// round 1
// baseline (speedup 1.0000x reference)
#include <cuda_runtime.h>
#include <math.h>

#define B_   128
#define T_   20
#define E_   512
#define H_   512
#define V_   32000
#define G4H  2048   // 4*H

// ---------------- scratch (static device globals; no allocation) ----------------
__device__ float g_Gx[T_ * B_ * G4H];   // x_t @ w_ih^T + bias, all steps  (20 MB)
__device__ float g_gates[B_ * G4H];     // per-step full gates
__device__ float g_hs[T_ * B_ * H_];    // all hidden states (time-major)
__device__ float g_c[B_ * H_];          // cell state
__device__ int   g_nt[T_];
__device__ int   g_off[T_ + 1];
__device__ int   g_local[T_ * B_];
__device__ int   g_rowmap[T_ * B_];     // packed row j -> t*B+b

// ---------------- pack-index machinery ----------------
__global__ void count_kernel(const int* __restrict__ lengths) {
    int t = blockIdx.x, b = threadIdx.x;
    int pred = lengths[b] > t;
    unsigned m = __ballot_sync(0xffffffffu, pred);
    int lane = b & 31, w = b >> 5;
    __shared__ int ws[4];
    if (lane == 0) ws[w] = __popc(m);
    __syncthreads();
    int prefix = 0;
#pragma unroll
    for (int i = 0; i < 4; i++) if (i < w) prefix += ws[i];
    g_local[t * B_ + b] = prefix + __popc(m & ((1u << lane) - 1u));
    if (b == 0) {
        int tot = 0;
#pragma unroll
        for (int i = 0; i < 4; i++) tot += ws[i];
        g_nt[t] = tot;
    }
}

__global__ void offset_kernel() {
    int o = 0;
    for (int t = 0; t < T_; t++) { g_off[t] = o; o += g_nt[t]; }
    g_off[T_] = o;
}

__global__ void scatter_kernel(const int* __restrict__ lengths) {
    int idx = blockIdx.x * 256 + threadIdx.x;
    if (idx >= T_ * B_) return;
    int t = idx >> 7, b = idx & 127;
    if (lengths[b] > t) g_rowmap[g_off[t] + g_local[idx]] = idx;
}

// ---------------- GEMM 1: Gx = [feat | embed(cap)] @ w_ih^T + (b_ih+b_hh) ----------------
// M = T*B = 2560, N = 4H = 2048, K = E = 512. Tile 64x64x16, 256 threads, 4x4 microtile.
__global__ void gx_gemm(const float* __restrict__ features,
                        const int*   __restrict__ captions,
                        const float* __restrict__ embed_w,
                        const float* __restrict__ w_ih,
                        const float* __restrict__ b_ih,
                        const float* __restrict__ b_hh) {
    __shared__ float As[16][64];
    __shared__ float Bs[16][64];
    int tid = threadIdx.x;
    int cn0 = blockIdx.x * 64;
    int rm0 = blockIdx.y * 64;
    int arow = tid >> 2, ac4 = (tid & 3) * 4;

    int r = rm0 + arow;
    int t = r >> 7, b = r & 127;
    const float* aptr;
    if (t == 0) aptr = features + (size_t)b * E_ + ac4;
    else        aptr = embed_w + (size_t)captions[b * T_ + (t - 1)] * E_ + ac4;
    const float* bptr = w_ih + (size_t)(cn0 + arow) * E_ + ac4;

    float acc[4][4] = {};
    int tm = tid >> 4, tn = tid & 15;

    for (int k0 = 0; k0 < E_; k0 += 16) {
        float4 a = *(const float4*)(aptr + k0);
        float4 bb = *(const float4*)(bptr + k0);
        As[ac4 + 0][arow] = a.x;  As[ac4 + 1][arow] = a.y;
        As[ac4 + 2][arow] = a.z;  As[ac4 + 3][arow] = a.w;
        Bs[ac4 + 0][arow] = bb.x; Bs[ac4 + 1][arow] = bb.y;
        Bs[ac4 + 2][arow] = bb.z; Bs[ac4 + 3][arow] = bb.w;
        __syncthreads();
#pragma unroll
        for (int kk = 0; kk < 16; kk++) {
            float4 av = *(const float4*)&As[kk][tm * 4];
            float4 bv = *(const float4*)&Bs[kk][tn * 4];
            float aa[4] = {av.x, av.y, av.z, av.w};
            float bvv[4] = {bv.x, bv.y, bv.z, bv.w};
#pragma unroll
            for (int i = 0; i < 4; i++)
#pragma unroll
                for (int j = 0; j < 4; j++) acc[i][j] += aa[i] * bvv[j];
        }
        __syncthreads();
    }

    int n = cn0 + tn * 4;
    float bias0 = b_ih[n + 0] + b_hh[n + 0];
    float bias1 = b_ih[n + 1] + b_hh[n + 1];
    float bias2 = b_ih[n + 2] + b_hh[n + 2];
    float bias3 = b_ih[n + 3] + b_hh[n + 3];
#pragma unroll
    for (int i = 0; i < 4; i++) {
        int rr = rm0 + tm * 4 + i;
        float4 o;
        o.x = acc[i][0] + bias0; o.y = acc[i][1] + bias1;
        o.z = acc[i][2] + bias2; o.w = acc[i][3] + bias3;
        *(float4*)&g_Gx[(size_t)rr * G4H + n] = o;
    }
}

// ---------------- GEMM 2 (per step): gates = Gx[t] + h_prev @ w_hh^T ----------------
// M = 128, N = 2048, K = 512. Same tile scheme, grid (32, 2).
__global__ void step_gemm(int t, const float* __restrict__ h0,
                          const float* __restrict__ w_hh) {
    __shared__ float As[16][64];
    __shared__ float Bs[16][64];
    int tid = threadIdx.x;
    int cn0 = blockIdx.x * 64;
    int rm0 = blockIdx.y * 64;
    int arow = tid >> 2, ac4 = (tid & 3) * 4;

    const float* hprev = (t == 0) ? h0 : (g_hs + (size_t)(t - 1) * B_ * H_);
    const float* aptr = hprev + (size_t)(rm0 + arow) * H_ + ac4;
    const float* bptr = w_hh + (size_t)(cn0 + arow) * H_ + ac4;

    float acc[4][4] = {};
    int tm = tid >> 4, tn = tid & 15;

    for (int k0 = 0; k0 < H_; k0 += 16) {
        float4 a = *(const float4*)(aptr + k0);
        float4 bb = *(const float4*)(bptr + k0);
        As[ac4 + 0][arow] = a.x;  As[ac4 + 1][arow] = a.y;
        As[ac4 + 2][arow] = a.z;  As[ac4 + 3][arow] = a.w;
        Bs[ac4 + 0][arow] = bb.x; Bs[ac4 + 1][arow] = bb.y;
        Bs[ac4 + 2][arow] = bb.z; Bs[ac4 + 3][arow] = bb.w;
        __syncthreads();
#pragma unroll
        for (int kk = 0; kk < 16; kk++) {
            float4 av = *(const float4*)&As[kk][tm * 4];
            float4 bv = *(const float4*)&Bs[kk][tn * 4];
            float aa[4] = {av.x, av.y, av.z, av.w};
            float bvv[4] = {bv.x, bv.y, bv.z, bv.w};
#pragma unroll
            for (int i = 0; i < 4; i++)
#pragma unroll
                for (int j = 0; j < 4; j++) acc[i][j] += aa[i] * bvv[j];
        }
        __syncthreads();
    }

    int n = cn0 + tn * 4;
#pragma unroll
    for (int i = 0; i < 4; i++) {
        int bb = rm0 + tm * 4 + i;
        const float4 gx = *(const float4*)&g_Gx[(size_t)(t * B_ + bb) * G4H + n];
        float4 o;
        o.x = acc[i][0] + gx.x; o.y = acc[i][1] + gx.y;
        o.z = acc[i][2] + gx.z; o.w = acc[i][3] + gx.w;
        *(float4*)&g_gates[(size_t)bb * G4H + n] = o;
    }
}

// ---------------- LSTM cell pointwise ----------------
__device__ __forceinline__ float sigmoidf(float x) { return 1.0f / (1.0f + expf(-x)); }

__global__ void cell_kernel(int t, const float* __restrict__ c0) {
    int idx = blockIdx.x * 256 + threadIdx.x;   // B*H = 65536 threads
    int b = idx >> 9, j = idx & 511;
    const float* gr = g_gates + (size_t)b * G4H;
    float ig = gr[j];
    float fg = gr[H_ + j];
    float gg = gr[2 * H_ + j];
    float og = gr[3 * H_ + j];
    float c = (t == 0) ? c0[idx] : g_c[idx];
    float cn = sigmoidf(fg) * c + sigmoidf(ig) * tanhf(gg);
    float h = sigmoidf(og) * tanhf(cn);
    g_c[idx] = cn;
    g_hs[(size_t)t * B_ * H_ + idx] = h;
}

// ---------------- GEMM 3: packed logits = hs[rowmap] @ lin_w^T + lin_b ----------------
// M = nrows (1600), N = V = 32000, K = 512. Tile 64x64x16, gather A rows via rowmap.
__global__ void out_gemm(const float* __restrict__ lin_w,
                         const float* __restrict__ lin_b,
                         float* __restrict__ out, int nrows) {
    __shared__ float As[16][64];
    __shared__ float Bs[16][64];
    __shared__ int rmap[64];
    int tid = threadIdx.x;
    int cn0 = blockIdx.x * 64;
    int rm0 = blockIdx.y * 64;

    if (tid < 64) {
        int j = rm0 + tid;
        rmap[tid] = (j < nrows) ? g_rowmap[j] : 0;
    }
    __syncthreads();

    int arow = tid >> 2, ac4 = (tid & 3) * 4;
    const float* aptr = g_hs + (size_t)rmap[arow] * H_ + ac4;
    const float* bptr = lin_w + (size_t)(cn0 + arow) * H_ + ac4;

    float acc[4][4] = {};
    int tm = tid >> 4, tn = tid & 15;

    for (int k0 = 0; k0 < H_; k0 += 16) {
        float4 a = *(const float4*)(aptr + k0);
        float4 bb = *(const float4*)(bptr + k0);
        As[ac4 + 0][arow] = a.x;  As[ac4 + 1][arow] = a.y;
        As[ac4 + 2][arow] = a.z;  As[ac4 + 3][arow] = a.w;
        Bs[ac4 + 0][arow] = bb.x; Bs[ac4 + 1][arow] = bb.y;
        Bs[ac4 + 2][arow] = bb.z; Bs[ac4 + 3][arow] = bb.w;
        __syncthreads();
#pragma unroll
        for (int kk = 0; kk < 16; kk++) {
            float4 av = *(const float4*)&As[kk][tm * 4];
            float4 bv = *(const float4*)&Bs[kk][tn * 4];
            float aa[4] = {av.x, av.y, av.z, av.w};
            float bvv[4] = {bv.x, bv.y, bv.z, bv.w};
#pragma unroll
            for (int i = 0; i < 4; i++)
#pragma unroll
                for (int j = 0; j < 4; j++) acc[i][j] += aa[i] * bvv[j];
        }
        __syncthreads();
    }

    int n = cn0 + tn * 4;
    float4 lb = *(const float4*)&lin_b[n];
#pragma unroll
    for (int i = 0; i < 4; i++) {
        int j = rm0 + tm * 4 + i;
        if (j < nrows) {
            float4 o;
            o.x = acc[i][0] + lb.x; o.y = acc[i][1] + lb.y;
            o.z = acc[i][2] + lb.z; o.w = acc[i][3] + lb.w;
            *(float4*)&out[(size_t)j * V_ + n] = o;
        }
    }
}

// ---------------- launch ----------------
extern "C" void kernel_launch(void* const* d_in, const int* in_sizes, int n_in,
                              void* d_out, int out_size) {
    const float* features = (const float*)d_in[0];
    const int*   captions = (const int*)d_in[1];
    const int*   lengths  = (const int*)d_in[2];
    const float* h0       = (const float*)d_in[3];
    const float* c0       = (const float*)d_in[4];
    const float* embed_w  = (const float*)d_in[5];
    const float* w_ih     = (const float*)d_in[6];
    const float* w_hh     = (const float*)d_in[7];
    const float* b_ih     = (const float*)d_in[8];
    const float* b_hh     = (const float*)d_in[9];
    const float* lin_w    = (const float*)d_in[10];
    const float* lin_b    = (const float*)d_in[11];
    float* out = (float*)d_out;
    int nrows = out_size / V_;

    // pack indices (independent of LSTM; enqueue first)
    count_kernel<<<T_, 128>>>(lengths);
    offset_kernel<<<1, 1>>>();
    scatter_kernel<<<(T_ * B_ + 255) / 256, 256>>>(lengths);

    // input projection for all timesteps at once
    gx_gemm<<<dim3(G4H / 64, (T_ * B_) / 64), 256>>>(features, captions, embed_w,
                                                     w_ih, b_ih, b_hh);

    // sequential recurrence
    for (int t = 0; t < T_; t++) {
        step_gemm<<<dim3(G4H / 64, B_ / 64), 256>>>(t, h0, w_hh);
        cell_kernel<<<(B_ * H_) / 256, 256>>>(t, c0);
    }

    // packed logits
    out_gemm<<<dim3(V_ / 64, (nrows + 63) / 64), 256>>>(lin_w, lin_b, out, nrows);
}

// round 3
// speedup vs baseline: 1.6216x; 1.6216x over previous
#include <cuda_runtime.h>
#include <cuda_bf16.h>
#include <math.h>
#include <cstdint>

#define B_   128
#define T_   20
#define E_   512
#define H_   512
#define V_   32000
#define G4H  2048   // 4*H
#define K2_  1536   // split-extended K

// ---------------- scratch (static device globals; no allocation) ----------------
__device__ float g_Gx[T_ * B_ * G4H];   // x_t @ w_ih^T + bias, all steps
__device__ float g_gates[B_ * G4H];     // per-step full gates
__device__ float g_hs[T_ * B_ * H_];    // all hidden states (time-major)
__device__ float g_c[B_ * H_];          // cell state
__device__ int   g_nt[T_];
__device__ int   g_off[T_ + 1];
__device__ int   g_local[T_ * B_];
__device__ int   g_rowmap[T_ * B_];     // packed row j -> t*B+b

// split-K bf16 operand images: A'' = [Ahi|Alo|Ahi], B'' = [Bhi|Bhi|Blo]
__device__ __align__(16) __nv_bfloat16 g_A2[1664u * K2_];     // 5.1 MB
__device__ __align__(16) __nv_bfloat16 g_B2[32000u * K2_];    // 98.3 MB

// ---------------- PTX helpers (sm_80-level: legal on plain sm_103 target) ----------------
__device__ __forceinline__ uint32_t smem_u32(const void* p) {
    uint32_t a;
    asm("{ .reg .u64 t; cvta.to.shared.u64 t, %1; cvt.u32.u64 %0, t; }" : "=r"(a) : "l"(p));
    return a;
}
__device__ __forceinline__ void cp_async16(uint32_t saddr, const void* g) {
    asm volatile("cp.async.cg.shared.global [%0], [%1], 16;" :: "r"(saddr), "l"(g));
}
__device__ __forceinline__ void ldsm_x4(uint32_t* r, uint32_t addr) {
    asm volatile("ldmatrix.sync.aligned.m8n8.x4.shared.b16 {%0,%1,%2,%3}, [%4];"
        : "=r"(r[0]), "=r"(r[1]), "=r"(r[2]), "=r"(r[3]) : "r"(addr));
}
__device__ __forceinline__ void mma_bf16(float* d, const uint32_t* a, const uint32_t* b) {
    asm volatile("mma.sync.aligned.m16n8k16.row.col.f32.bf16.bf16.f32 "
        "{%0,%1,%2,%3}, {%4,%5,%6,%7}, {%8,%9}, {%0,%1,%2,%3};"
        : "+f"(d[0]), "+f"(d[1]), "+f"(d[2]), "+f"(d[3])
        : "r"(a[0]), "r"(a[1]), "r"(a[2]), "r"(a[3]), "r"(b[0]), "r"(b[1]));
}

// ---------------- pack-index machinery ----------------
__global__ void count_kernel(const int* __restrict__ lengths) {
    int t = blockIdx.x, b = threadIdx.x;
    int pred = lengths[b] > t;
    unsigned m = __ballot_sync(0xffffffffu, pred);
    int lane = b & 31, w = b >> 5;
    __shared__ int ws[4];
    if (lane == 0) ws[w] = __popc(m);
    __syncthreads();
    int prefix = 0;
#pragma unroll
    for (int i = 0; i < 4; i++) if (i < w) prefix += ws[i];
    g_local[t * B_ + b] = prefix + __popc(m & ((1u << lane) - 1u));
    if (b == 0) {
        int tot = 0;
#pragma unroll
        for (int i = 0; i < 4; i++) tot += ws[i];
        g_nt[t] = tot;
    }
}

__global__ void offset_kernel() {
    int o = 0;
    for (int t = 0; t < T_; t++) { g_off[t] = o; o += g_nt[t]; }
    g_off[T_] = o;
}

__global__ void scatter_kernel(const int* __restrict__ lengths) {
    int idx = blockIdx.x * 256 + threadIdx.x;
    if (idx >= T_ * B_) return;
    int t = idx >> 7, b = idx & 127;
    if (lengths[b] > t) g_rowmap[g_off[t] + g_local[idx]] = idx;
}

// ---------------- GEMM 1: Gx = [feat | embed(cap)] @ w_ih^T + (b_ih+b_hh) ----------------
__global__ void gx_gemm(const float* __restrict__ features,
                        const int*   __restrict__ captions,
                        const float* __restrict__ embed_w,
                        const float* __restrict__ w_ih,
                        const float* __restrict__ b_ih,
                        const float* __restrict__ b_hh) {
    __shared__ float As[16][64];
    __shared__ float Bs[16][64];
    int tid = threadIdx.x;
    int cn0 = blockIdx.x * 64;
    int rm0 = blockIdx.y * 64;
    int arow = tid >> 2, ac4 = (tid & 3) * 4;

    int r = rm0 + arow;
    int t = r >> 7, b = r & 127;
    const float* aptr;
    if (t == 0) aptr = features + (size_t)b * E_ + ac4;
    else        aptr = embed_w + (size_t)captions[b * T_ + (t - 1)] * E_ + ac4;
    const float* bptr = w_ih + (size_t)(cn0 + arow) * E_ + ac4;

    float acc[4][4] = {};
    int tm = tid >> 4, tn = tid & 15;

    for (int k0 = 0; k0 < E_; k0 += 16) {
        float4 a = *(const float4*)(aptr + k0);
        float4 bb = *(const float4*)(bptr + k0);
        As[ac4 + 0][arow] = a.x;  As[ac4 + 1][arow] = a.y;
        As[ac4 + 2][arow] = a.z;  As[ac4 + 3][arow] = a.w;
        Bs[ac4 + 0][arow] = bb.x; Bs[ac4 + 1][arow] = bb.y;
        Bs[ac4 + 2][arow] = bb.z; Bs[ac4 + 3][arow] = bb.w;
        __syncthreads();
#pragma unroll
        for (int kk = 0; kk < 16; kk++) {
            float4 av = *(const float4*)&As[kk][tm * 4];
            float4 bv = *(const float4*)&Bs[kk][tn * 4];
            float aa[4] = {av.x, av.y, av.z, av.w};
            float bvv[4] = {bv.x, bv.y, bv.z, bv.w};
#pragma unroll
            for (int i = 0; i < 4; i++)
#pragma unroll
                for (int j = 0; j < 4; j++) acc[i][j] += aa[i] * bvv[j];
        }
        __syncthreads();
    }

    int n = cn0 + tn * 4;
    float bias0 = b_ih[n + 0] + b_hh[n + 0];
    float bias1 = b_ih[n + 1] + b_hh[n + 1];
    float bias2 = b_ih[n + 2] + b_hh[n + 2];
    float bias3 = b_ih[n + 3] + b_hh[n + 3];
#pragma unroll
    for (int i = 0; i < 4; i++) {
        int rr = rm0 + tm * 4 + i;
        float4 o;
        o.x = acc[i][0] + bias0; o.y = acc[i][1] + bias1;
        o.z = acc[i][2] + bias2; o.w = acc[i][3] + bias3;
        *(float4*)&g_Gx[(size_t)rr * G4H + n] = o;
    }
}

// ---------------- GEMM 2 (per step): gates = Gx[t] + h_prev @ w_hh^T ----------------
__global__ void step_gemm(int t, const float* __restrict__ h0,
                          const float* __restrict__ w_hh) {
    __shared__ float As[16][64];
    __shared__ float Bs[16][64];
    int tid = threadIdx.x;
    int cn0 = blockIdx.x * 64;
    int rm0 = blockIdx.y * 64;
    int arow = tid >> 2, ac4 = (tid & 3) * 4;

    const float* hprev = (t == 0) ? h0 : (g_hs + (size_t)(t - 1) * B_ * H_);
    const float* aptr = hprev + (size_t)(rm0 + arow) * H_ + ac4;
    const float* bptr = w_hh + (size_t)(cn0 + arow) * H_ + ac4;

    float acc[4][4] = {};
    int tm = tid >> 4, tn = tid & 15;

    for (int k0 = 0; k0 < H_; k0 += 16) {
        float4 a = *(const float4*)(aptr + k0);
        float4 bb = *(const float4*)(bptr + k0);
        As[ac4 + 0][arow] = a.x;  As[ac4 + 1][arow] = a.y;
        As[ac4 + 2][arow] = a.z;  As[ac4 + 3][arow] = a.w;
        Bs[ac4 + 0][arow] = bb.x; Bs[ac4 + 1][arow] = bb.y;
        Bs[ac4 + 2][arow] = bb.z; Bs[ac4 + 3][arow] = bb.w;
        __syncthreads();
#pragma unroll
        for (int kk = 0; kk < 16; kk++) {
            float4 av = *(const float4*)&As[kk][tm * 4];
            float4 bv = *(const float4*)&Bs[kk][tn * 4];
            float aa[4] = {av.x, av.y, av.z, av.w};
            float bvv[4] = {bv.x, bv.y, bv.z, bv.w};
#pragma unroll
            for (int i = 0; i < 4; i++)
#pragma unroll
                for (int j = 0; j < 4; j++) acc[i][j] += aa[i] * bvv[j];
        }
        __syncthreads();
    }

    int n = cn0 + tn * 4;
#pragma unroll
    for (int i = 0; i < 4; i++) {
        int bb = rm0 + tm * 4 + i;
        const float4 gx = *(const float4*)&g_Gx[(size_t)(t * B_ + bb) * G4H + n];
        float4 o;
        o.x = acc[i][0] + gx.x; o.y = acc[i][1] + gx.y;
        o.z = acc[i][2] + gx.z; o.w = acc[i][3] + gx.w;
        *(float4*)&g_gates[(size_t)bb * G4H + n] = o;
    }
}

// ---------------- LSTM cell pointwise ----------------
__device__ __forceinline__ float sigmoidf_(float x) { return 1.0f / (1.0f + expf(-x)); }

__global__ void cell_kernel(int t, const float* __restrict__ c0) {
    int idx = blockIdx.x * 256 + threadIdx.x;
    int b = idx >> 9, j = idx & 511;
    const float* gr = g_gates + (size_t)b * G4H;
    float ig = gr[j];
    float fg = gr[H_ + j];
    float gg = gr[2 * H_ + j];
    float og = gr[3 * H_ + j];
    float c = (t == 0) ? c0[idx] : g_c[idx];
    float cn = sigmoidf_(fg) * c + sigmoidf_(ig) * tanhf(gg);
    float h = sigmoidf_(og) * tanhf(cn);
    g_c[idx] = cn;
    g_hs[(size_t)t * B_ * H_ + idx] = h;
}

// ---------------- split-K operand builders ----------------
// B'' = [Bhi | Bhi | Blo] along K
__global__ void convert_B(const float* __restrict__ lin_w) {
    int idx = blockIdx.x * 256 + threadIdx.x;   // V_*512
    int n = idx >> 9, k = idx & 511;
    float v = lin_w[(size_t)n * 512 + k];
    __nv_bfloat16 hi = __float2bfloat16(v);
    __nv_bfloat16 lo = __float2bfloat16(v - __bfloat162float(hi));
    size_t base = (size_t)n * K2_ + k;
    g_B2[base] = hi;
    g_B2[base + 512] = hi;
    g_B2[base + 1024] = lo;
}

// A'' = [Ahi | Alo | Ahi] along K, rows gathered via g_rowmap (pad -> row 0 junk)
__global__ void convert_A() {
    int idx = blockIdx.x * 256 + threadIdx.x;   // 1664*512
    int m = idx >> 9, k = idx & 511;
    int nr = g_off[T_];
    int src = (m < nr) ? g_rowmap[m] : 0;
    float v = g_hs[(size_t)src * 512 + k];
    __nv_bfloat16 hi = __float2bfloat16(v);
    __nv_bfloat16 lo = __float2bfloat16(v - __bfloat162float(hi));
    size_t base = (size_t)m * K2_ + k;
    g_A2[base] = hi;
    g_A2[base + 512] = lo;
    g_A2[base + 1024] = hi;
}

// ---------------- GEMM 3 (mma.sync bf16): out = A'' @ B''^T + lin_b ----------------
// CTA tile 128x128, K-chunk 64, 2-stage cp.async pipeline, 8 warps each 64x32.
// smem: per stage A[128 rows x 144B] + B[128 x 144B] = 36864B; 2 stages = 73728B.
#define RS_      144
#define STAGE_   36864
#define NCHUNK_  (K2_ / 64)   // 24

__global__ void __launch_bounds__(256, 1) out_gemm_mma(const float* __restrict__ lin_b,
                                                       float* __restrict__ out, int nrows) {
    extern __shared__ char smem[];
    uint32_t sb = smem_u32(smem);
    int tid = threadIdx.x, lane = tid & 31, wid = tid >> 5;
    int n0 = blockIdx.x * 128, m0 = blockIdx.y * 128;
    int wm = (wid >> 2) * 64, wn = (wid & 3) * 32;

    float acc[4][4][4] = {};

    // stage loader: 128 rows x 8 chunks of 16B for A and B each
#define LOAD_STAGE(s, kc) do { \
        uint32_t base_ = sb + (s) * STAGE_; \
        int k0_ = (kc) * 64; \
        for (int i = tid; i < 1024; i += 256) { \
            int r_ = i >> 3, c_ = i & 7; \
            cp_async16(base_ + r_ * RS_ + c_ * 16, \
                       g_A2 + (size_t)(m0 + r_) * K2_ + k0_ + c_ * 8); \
            cp_async16(base_ + 18432 + r_ * RS_ + c_ * 16, \
                       g_B2 + (size_t)(n0 + r_) * K2_ + k0_ + c_ * 8); \
        } \
        asm volatile("cp.async.commit_group;" ::: "memory"); \
    } while (0)

    LOAD_STAGE(0, 0);
    LOAD_STAGE(1, 1);

    for (int kc = 0; kc < NCHUNK_; kc++) {
        asm volatile("cp.async.wait_group 1;" ::: "memory");
        __syncthreads();
        int s = kc & 1;
        uint32_t sA = sb + s * STAGE_;
        uint32_t sB = sA + 18432;
        // ldmatrix lane addresses
        uint32_t aA = sA + (uint32_t)(wm + (lane & 15)) * RS_ + ((lane >> 4) << 4);
        uint32_t aB = sB + (uint32_t)(wn + (lane & 7) + ((lane & 16) >> 1)) * RS_ + ((lane & 8) << 1);
#pragma unroll
        for (int st = 0; st < 4; st++) {
            uint32_t af[4][4], bfr[2][4];
#pragma unroll
            for (int ta = 0; ta < 4; ta++) ldsm_x4(af[ta], aA + ta * (16 * RS_) + st * 32);
#pragma unroll
            for (int tb = 0; tb < 2; tb++) ldsm_x4(bfr[tb], aB + tb * (16 * RS_) + st * 32);
#pragma unroll
            for (int ta = 0; ta < 4; ta++)
#pragma unroll
                for (int tn = 0; tn < 4; tn++)
                    mma_bf16(acc[ta][tn], af[ta], &bfr[tn >> 1][(tn & 1) * 2]);
        }
        __syncthreads();
        if (kc + 2 < NCHUNK_) {
            LOAD_STAGE(s, kc + 2);
        } else {
            asm volatile("cp.async.commit_group;" ::: "memory");
        }
    }

    // epilogue
    int g = lane >> 2, tc2 = (lane & 3) * 2;
#pragma unroll
    for (int ta = 0; ta < 4; ta++) {
        int j0 = m0 + wm + ta * 16 + g;
        int j1 = j0 + 8;
#pragma unroll
        for (int tn = 0; tn < 4; tn++) {
            int col = n0 + wn + tn * 8 + tc2;
            float2 lb = *(const float2*)&lin_b[col];
            if (j0 < nrows) {
                float2 o = {acc[ta][tn][0] + lb.x, acc[ta][tn][1] + lb.y};
                *(float2*)&out[(size_t)j0 * V_ + col] = o;
            }
            if (j1 < nrows) {
                float2 o = {acc[ta][tn][2] + lb.x, acc[ta][tn][3] + lb.y};
                *(float2*)&out[(size_t)j1 * V_ + col] = o;
            }
        }
    }
#undef LOAD_STAGE
}

// ---------------- launch ----------------
extern "C" void kernel_launch(void* const* d_in, const int* in_sizes, int n_in,
                              void* d_out, int out_size) {
    const float* features = (const float*)d_in[0];
    const int*   captions = (const int*)d_in[1];
    const int*   lengths  = (const int*)d_in[2];
    const float* h0       = (const float*)d_in[3];
    const float* c0       = (const float*)d_in[4];
    const float* embed_w  = (const float*)d_in[5];
    const float* w_ih     = (const float*)d_in[6];
    const float* w_hh     = (const float*)d_in[7];
    const float* b_ih     = (const float*)d_in[8];
    const float* b_hh     = (const float*)d_in[9];
    const float* lin_w    = (const float*)d_in[10];
    const float* lin_b    = (const float*)d_in[11];
    float* out = (float*)d_out;
    int nrows = out_size / V_;

    cudaFuncSetAttribute(out_gemm_mma, cudaFuncAttributeMaxDynamicSharedMemorySize,
                         2 * STAGE_);

    // pack indices
    count_kernel<<<T_, 128>>>(lengths);
    offset_kernel<<<1, 1>>>();
    scatter_kernel<<<(T_ * B_ + 255) / 256, 256>>>(lengths);

    // B'' build (independent of recurrence — overlaps with it in-stream order)
    convert_B<<<(V_ * 512) / 256, 256>>>(lin_w);

    // input projection for all timesteps at once
    gx_gemm<<<dim3(G4H / 64, (T_ * B_) / 64), 256>>>(features, captions, embed_w,
                                                     w_ih, b_ih, b_hh);

    // sequential recurrence
    for (int t = 0; t < T_; t++) {
        step_gemm<<<dim3(G4H / 64, B_ / 64), 256>>>(t, h0, w_hh);
        cell_kernel<<<(B_ * H_) / 256, 256>>>(t, c0);
    }

    // A'' build (packed-row gather + split)
    convert_A<<<(1664 * 512) / 256, 256>>>();

    // tensor-core packed logits
    int mtiles = (nrows + 127) / 128;   // 13
    out_gemm_mma<<<dim3(V_ / 128, mtiles), 256, 2 * STAGE_>>>(lin_b, out, nrows);
}

// round 6
// speedup vs baseline: 2.1653x; 1.3353x over previous
#include <cuda_runtime.h>
#include <cuda_fp16.h>
#include <math.h>
#include <cstdint>

#define B_   128
#define T_   20
#define E_   512
#define H_   512
#define V_   32000
#define G4H  2048   // 4*H

// ---------------- scratch (static device globals; no allocation) ----------------
__device__ float g_Gx[T_ * B_ * G4H];   // x_t @ w_ih^T + bias, all steps
__device__ float g_gates[B_ * G4H];     // per-step full gates
__device__ float g_hs[T_ * B_ * H_];    // all hidden states (time-major)
__device__ float g_c[B_ * H_];          // cell state
__device__ int   g_nt[T_];
__device__ int   g_off[T_ + 1];
__device__ int   g_local[T_ * B_];
__device__ int   g_rowmap[T_ * B_];     // packed row j -> t*B+b

// single-fp16 operand images for the out GEMM
__device__ __align__(16) __half g_Ah[1664u * 512u];    // packed h rows
__device__ __align__(16) __half g_Bh[32000u * 512u];   // lin_w rows

// ---------------- PTX helpers (sm_80-level; legal on plain sm_103 target) ----------------
__device__ __forceinline__ uint32_t smem_u32(const void* p) {
    uint32_t a;
    asm("{ .reg .u64 t; cvta.to.shared.u64 t, %1; cvt.u32.u64 %0, t; }" : "=r"(a) : "l"(p));
    return a;
}
__device__ __forceinline__ void cp_async16(uint32_t saddr, const void* g) {
    asm volatile("cp.async.cg.shared.global [%0], [%1], 16;" :: "r"(saddr), "l"(g));
}
__device__ __forceinline__ void ldsm_x4(uint32_t* r, uint32_t addr) {
    asm volatile("ldmatrix.sync.aligned.m8n8.x4.shared.b16 {%0,%1,%2,%3}, [%4];"
        : "=r"(r[0]), "=r"(r[1]), "=r"(r[2]), "=r"(r[3]) : "r"(addr));
}
__device__ __forceinline__ void mma_fp16(float* d, const uint32_t* a, const uint32_t* b) {
    asm volatile("mma.sync.aligned.m16n8k16.row.col.f32.f16.f16.f32 "
        "{%0,%1,%2,%3}, {%4,%5,%6,%7}, {%8,%9}, {%0,%1,%2,%3};"
        : "+f"(d[0]), "+f"(d[1]), "+f"(d[2]), "+f"(d[3])
        : "r"(a[0]), "r"(a[1]), "r"(a[2]), "r"(a[3]), "r"(b[0]), "r"(b[1]));
}

// ---------------- pack-index machinery ----------------
__global__ void count_kernel(const int* __restrict__ lengths) {
    int t = blockIdx.x, b = threadIdx.x;
    int pred = lengths[b] > t;
    unsigned m = __ballot_sync(0xffffffffu, pred);
    int lane = b & 31, w = b >> 5;
    __shared__ int ws[4];
    if (lane == 0) ws[w] = __popc(m);
    __syncthreads();
    int prefix = 0;
#pragma unroll
    for (int i = 0; i < 4; i++) if (i < w) prefix += ws[i];
    g_local[t * B_ + b] = prefix + __popc(m & ((1u << lane) - 1u));
    if (b == 0) {
        int tot = 0;
#pragma unroll
        for (int i = 0; i < 4; i++) tot += ws[i];
        g_nt[t] = tot;
    }
}

__global__ void offset_kernel() {
    int o = 0;
    for (int t = 0; t < T_; t++) { g_off[t] = o; o += g_nt[t]; }
    g_off[T_] = o;
}

__global__ void scatter_kernel(const int* __restrict__ lengths) {
    int idx = blockIdx.x * 256 + threadIdx.x;
    if (idx >= T_ * B_) return;
    int t = idx >> 7, b = idx & 127;
    if (lengths[b] > t) g_rowmap[g_off[t] + g_local[idx]] = idx;
}

// ---------------- GEMM 1 (fp32 SIMT, proven): Gx = [feat|embed] @ w_ih^T + bias ----------------
__global__ void gx_gemm(const float* __restrict__ features,
                        const int*   __restrict__ captions,
                        const float* __restrict__ embed_w,
                        const float* __restrict__ w_ih,
                        const float* __restrict__ b_ih,
                        const float* __restrict__ b_hh) {
    __shared__ float As[16][64];
    __shared__ float Bs[16][64];
    int tid = threadIdx.x;
    int cn0 = blockIdx.x * 64;
    int rm0 = blockIdx.y * 64;
    int arow = tid >> 2, ac4 = (tid & 3) * 4;

    int r = rm0 + arow;
    int t = r >> 7, b = r & 127;
    const float* aptr;
    if (t == 0) aptr = features + (size_t)b * E_ + ac4;
    else        aptr = embed_w + (size_t)captions[b * T_ + (t - 1)] * E_ + ac4;
    const float* bptr = w_ih + (size_t)(cn0 + arow) * E_ + ac4;

    float acc[4][4] = {};
    int tm = tid >> 4, tn = tid & 15;

    for (int k0 = 0; k0 < E_; k0 += 16) {
        float4 a = *(const float4*)(aptr + k0);
        float4 bb = *(const float4*)(bptr + k0);
        As[ac4 + 0][arow] = a.x;  As[ac4 + 1][arow] = a.y;
        As[ac4 + 2][arow] = a.z;  As[ac4 + 3][arow] = a.w;
        Bs[ac4 + 0][arow] = bb.x; Bs[ac4 + 1][arow] = bb.y;
        Bs[ac4 + 2][arow] = bb.z; Bs[ac4 + 3][arow] = bb.w;
        __syncthreads();
#pragma unroll
        for (int kk = 0; kk < 16; kk++) {
            float4 av = *(const float4*)&As[kk][tm * 4];
            float4 bv = *(const float4*)&Bs[kk][tn * 4];
            float aa[4] = {av.x, av.y, av.z, av.w};
            float bvv[4] = {bv.x, bv.y, bv.z, bv.w};
#pragma unroll
            for (int i = 0; i < 4; i++)
#pragma unroll
                for (int j = 0; j < 4; j++) acc[i][j] += aa[i] * bvv[j];
        }
        __syncthreads();
    }

    int n = cn0 + tn * 4;
    float bias0 = b_ih[n + 0] + b_hh[n + 0];
    float bias1 = b_ih[n + 1] + b_hh[n + 1];
    float bias2 = b_ih[n + 2] + b_hh[n + 2];
    float bias3 = b_ih[n + 3] + b_hh[n + 3];
#pragma unroll
    for (int i = 0; i < 4; i++) {
        int rr = rm0 + tm * 4 + i;
        float4 o;
        o.x = acc[i][0] + bias0; o.y = acc[i][1] + bias1;
        o.z = acc[i][2] + bias2; o.w = acc[i][3] + bias3;
        *(float4*)&g_Gx[(size_t)rr * G4H + n] = o;
    }
}

// ---------------- GEMM 2 (fp32 SIMT, proven): gates = Gx[t] + h_prev @ w_hh^T ----------------
__global__ void step_gemm(int t, const float* __restrict__ h0,
                          const float* __restrict__ w_hh) {
    __shared__ float As[16][64];
    __shared__ float Bs[16][64];
    int tid = threadIdx.x;
    int cn0 = blockIdx.x * 64;
    int rm0 = blockIdx.y * 64;
    int arow = tid >> 2, ac4 = (tid & 3) * 4;

    const float* hprev = (t == 0) ? h0 : (g_hs + (size_t)(t - 1) * B_ * H_);
    const float* aptr = hprev + (size_t)(rm0 + arow) * H_ + ac4;
    const float* bptr = w_hh + (size_t)(cn0 + arow) * H_ + ac4;

    float acc[4][4] = {};
    int tm = tid >> 4, tn = tid & 15;

    for (int k0 = 0; k0 < H_; k0 += 16) {
        float4 a = *(const float4*)(aptr + k0);
        float4 bb = *(const float4*)(bptr + k0);
        As[ac4 + 0][arow] = a.x;  As[ac4 + 1][arow] = a.y;
        As[ac4 + 2][arow] = a.z;  As[ac4 + 3][arow] = a.w;
        Bs[ac4 + 0][arow] = bb.x; Bs[ac4 + 1][arow] = bb.y;
        Bs[ac4 + 2][arow] = bb.z; Bs[ac4 + 3][arow] = bb.w;
        __syncthreads();
#pragma unroll
        for (int kk = 0; kk < 16; kk++) {
            float4 av = *(const float4*)&As[kk][tm * 4];
            float4 bv = *(const float4*)&Bs[kk][tn * 4];
            float aa[4] = {av.x, av.y, av.z, av.w};
            float bvv[4] = {bv.x, bv.y, bv.z, bv.w};
#pragma unroll
            for (int i = 0; i < 4; i++)
#pragma unroll
                for (int j = 0; j < 4; j++) acc[i][j] += aa[i] * bvv[j];
        }
        __syncthreads();
    }

    int n = cn0 + tn * 4;
#pragma unroll
    for (int i = 0; i < 4; i++) {
        int bb = rm0 + tm * 4 + i;
        const float4 gx = *(const float4*)&g_Gx[(size_t)(t * B_ + bb) * G4H + n];
        float4 o;
        o.x = acc[i][0] + gx.x; o.y = acc[i][1] + gx.y;
        o.z = acc[i][2] + gx.z; o.w = acc[i][3] + gx.w;
        *(float4*)&g_gates[(size_t)bb * G4H + n] = o;
    }
}

// ---------------- LSTM cell pointwise (proven) ----------------
__device__ __forceinline__ float sigmoidf_(float x) { return 1.0f / (1.0f + expf(-x)); }

__global__ void cell_kernel(int t, const float* __restrict__ c0) {
    int idx = blockIdx.x * 256 + threadIdx.x;
    int b = idx >> 9, j = idx & 511;
    const float* gr = g_gates + (size_t)b * G4H;
    float ig = gr[j];
    float fg = gr[H_ + j];
    float gg = gr[2 * H_ + j];
    float og = gr[3 * H_ + j];
    float c = (t == 0) ? c0[idx] : g_c[idx];
    float cn = sigmoidf_(fg) * c + sigmoidf_(ig) * tanhf(gg);
    float h = sigmoidf_(og) * tanhf(cn);
    g_c[idx] = cn;
    g_hs[(size_t)t * B_ * H_ + idx] = h;
}

// ---------------- converters: single fp16 ----------------
__global__ void convert_Bout(const float* __restrict__ lin_w) {
    int idx = blockIdx.x * 256 + threadIdx.x;   // 32000*512
    g_Bh[idx] = __float2half(lin_w[idx]);
}

__global__ void convert_Aout() {
    int idx = blockIdx.x * 256 + threadIdx.x;   // 1664*512
    int m = idx >> 9;
    int nr = g_off[T_];
    int src = (m < nr) ? g_rowmap[m] : 0;
    g_Ah[idx] = __float2half(g_hs[(size_t)src * 512 + (idx & 511)]);
}

// ---------------- GEMM 3 (mma.sync fp16, K=512): out = Ah @ Bh^T + lin_b ----------------
// Identical template to R3's passing out_gemm_mma; only dtype/K changed.
#define RS_      144
#define STAGE_   36864
#define NCHUNK_  8   // K=512 / 64

__global__ void __launch_bounds__(256, 1) out_gemm_mma(const float* __restrict__ lin_b,
                                                       float* __restrict__ out, int nrows) {
    extern __shared__ char smem[];
    uint32_t sb = smem_u32(smem);
    int tid = threadIdx.x, lane = tid & 31, wid = tid >> 5;
    int n0 = blockIdx.x * 128, m0 = blockIdx.y * 128;
    int wm = (wid >> 2) * 64, wn = (wid & 3) * 32;

    float acc[4][4][4] = {};

#define LOAD_STAGE(s, kc) do { \
        uint32_t base_ = sb + (s) * STAGE_; \
        int k0_ = (kc) * 64; \
        for (int i = tid; i < 1024; i += 256) { \
            int r_ = i >> 3, c_ = i & 7; \
            cp_async16(base_ + r_ * RS_ + c_ * 16, \
                       g_Ah + (size_t)(m0 + r_) * 512 + k0_ + c_ * 8); \
            cp_async16(base_ + 18432 + r_ * RS_ + c_ * 16, \
                       g_Bh + (size_t)(n0 + r_) * 512 + k0_ + c_ * 8); \
        } \
        asm volatile("cp.async.commit_group;" ::: "memory"); \
    } while (0)

    LOAD_STAGE(0, 0);
    LOAD_STAGE(1, 1);

    for (int kc = 0; kc < NCHUNK_; kc++) {
        asm volatile("cp.async.wait_group 1;" ::: "memory");
        __syncthreads();
        int s = kc & 1;
        uint32_t sA = sb + s * STAGE_;
        uint32_t sB = sA + 18432;
        uint32_t aA = sA + (uint32_t)(wm + (lane & 15)) * RS_ + ((lane >> 4) << 4);
        uint32_t aB = sB + (uint32_t)(wn + (lane & 7) + ((lane & 16) >> 1)) * RS_ + ((lane & 8) << 1);
#pragma unroll
        for (int st = 0; st < 4; st++) {
            uint32_t af[4][4], bfr[2][4];
#pragma unroll
            for (int ta = 0; ta < 4; ta++) ldsm_x4(af[ta], aA + ta * (16 * RS_) + st * 32);
#pragma unroll
            for (int tb = 0; tb < 2; tb++) ldsm_x4(bfr[tb], aB + tb * (16 * RS_) + st * 32);
#pragma unroll
            for (int ta = 0; ta < 4; ta++)
#pragma unroll
                for (int tn = 0; tn < 4; tn++)
                    mma_fp16(acc[ta][tn], af[ta], &bfr[tn >> 1][(tn & 1) * 2]);
        }
        __syncthreads();
        if (kc + 2 < NCHUNK_) {
            LOAD_STAGE(s, kc + 2);
        } else {
            asm volatile("cp.async.commit_group;" ::: "memory");
        }
    }
#undef LOAD_STAGE

    // epilogue
    int g = lane >> 2, tc2 = (lane & 3) * 2;
#pragma unroll
    for (int ta = 0; ta < 4; ta++) {
        int j0 = m0 + wm + ta * 16 + g;
        int j1 = j0 + 8;
#pragma unroll
        for (int tn = 0; tn < 4; tn++) {
            int col = n0 + wn + tn * 8 + tc2;
            float2 lb = *(const float2*)&lin_b[col];
            if (j0 < nrows) {
                float2 o = {acc[ta][tn][0] + lb.x, acc[ta][tn][1] + lb.y};
                *(float2*)&out[(size_t)j0 * V_ + col] = o;
            }
            if (j1 < nrows) {
                float2 o = {acc[ta][tn][2] + lb.x, acc[ta][tn][3] + lb.y};
                *(float2*)&out[(size_t)j1 * V_ + col] = o;
            }
        }
    }
}

// ---------------- launch ----------------
extern "C" void kernel_launch(void* const* d_in, const int* in_sizes, int n_in,
                              void* d_out, int out_size) {
    const float* features = (const float*)d_in[0];
    const int*   captions = (const int*)d_in[1];
    const int*   lengths  = (const int*)d_in[2];
    const float* h0       = (const float*)d_in[3];
    const float* c0       = (const float*)d_in[4];
    const float* embed_w  = (const float*)d_in[5];
    const float* w_ih     = (const float*)d_in[6];
    const float* w_hh     = (const float*)d_in[7];
    const float* b_ih     = (const float*)d_in[8];
    const float* b_hh     = (const float*)d_in[9];
    const float* lin_w    = (const float*)d_in[10];
    const float* lin_b    = (const float*)d_in[11];
    float* out = (float*)d_out;
    int nrows = out_size / V_;

    cudaFuncSetAttribute(out_gemm_mma, cudaFuncAttributeMaxDynamicSharedMemorySize,
                         2 * STAGE_);

    // pack indices
    count_kernel<<<T_, 128>>>(lengths);
    offset_kernel<<<1, 1>>>();
    scatter_kernel<<<(T_ * B_ + 255) / 256, 256>>>(lengths);

    // B operand build (independent of recurrence)
    convert_Bout<<<(V_ * 512) / 256, 256>>>(lin_w);

    // input projection for all timesteps at once (fp32, proven)
    gx_gemm<<<dim3(G4H / 64, (T_ * B_) / 64), 256>>>(features, captions, embed_w,
                                                     w_ih, b_ih, b_hh);

    // sequential recurrence (fp32, proven)
    for (int t = 0; t < T_; t++) {
        step_gemm<<<dim3(G4H / 64, B_ / 64), 256>>>(t, h0, w_hh);
        cell_kernel<<<(B_ * H_) / 256, 256>>>(t, c0);
    }

    // A operand build (packed-row gather)
    convert_Aout<<<(1664 * 512) / 256, 256>>>();

    // tensor-core packed logits (single fp16)
    int mtiles = (nrows + 127) / 128;   // 13
    out_gemm_mma<<<dim3(V_ / 128, mtiles), 256, 2 * STAGE_>>>(lin_b, out, nrows);
}

// round 9
// speedup vs baseline: 3.4807x; 1.6075x over previous
#include <cuda_runtime.h>
#include <cuda_fp16.h>
#include <math.h>
#include <cstdint>

#define B_   128
#define T_   20
#define E_   512
#define H_   512
#define V_   32000
#define G4H  2048   // 4*H
#define K3_  1536   // 3-term split-extended K (recurrence only)
#define NSPLIT 8

// ---------------- scratch (static device globals; no allocation) ----------------
__device__ float g_Gx[T_ * B_ * G4H];   // x_t @ w_ih^T + bias, all steps
__device__ float g_hs[T_ * B_ * H_];    // all hidden states (time-major)
__device__ float g_c[B_ * H_];          // cell state ([j*128+b] layout)
__device__ float g_part[NSPLIT * G4H * B_];  // split-K partials [split][n][b]  8MB
__device__ int   g_nt[T_];
__device__ int   g_off[T_ + 1];
__device__ int   g_local[T_ * B_];
__device__ int   g_rowmap[T_ * B_];     // packed row j -> t*B+b

// recurrence fp16 3-term operands
__device__ __align__(16) __half g_Whh[G4H * K3_];      // [whi|whi|wlo]
__device__ __align__(16) __half g_h2[2][B_ * K3_];     // ping-pong [hhi|hlo|hhi]
// out-GEMM single-fp16 operands
__device__ __align__(16) __half g_Ah[1664u * 512u];    // packed h rows
__device__ __align__(16) __half g_Bh[32000u * 512u];   // lin_w rows

// ---------------- PTX helpers (sm_80-level; legal on plain sm_103 target) ----------------
__device__ __forceinline__ uint32_t smem_u32(const void* p) {
    uint32_t a;
    asm("{ .reg .u64 t; cvta.to.shared.u64 t, %1; cvt.u32.u64 %0, t; }" : "=r"(a) : "l"(p));
    return a;
}
__device__ __forceinline__ void cp_async16(uint32_t saddr, const void* g) {
    asm volatile("cp.async.cg.shared.global [%0], [%1], 16;" :: "r"(saddr), "l"(g));
}
__device__ __forceinline__ void ldsm_x4(uint32_t* r, uint32_t addr) {
    asm volatile("ldmatrix.sync.aligned.m8n8.x4.shared.b16 {%0,%1,%2,%3}, [%4];"
        : "=r"(r[0]), "=r"(r[1]), "=r"(r[2]), "=r"(r[3]) : "r"(addr));
}
__device__ __forceinline__ void mma_fp16(float* d, const uint32_t* a, const uint32_t* b) {
    asm volatile("mma.sync.aligned.m16n8k16.row.col.f32.f16.f16.f32 "
        "{%0,%1,%2,%3}, {%4,%5,%6,%7}, {%8,%9}, {%0,%1,%2,%3};"
        : "+f"(d[0]), "+f"(d[1]), "+f"(d[2]), "+f"(d[3])
        : "r"(a[0]), "r"(a[1]), "r"(a[2]), "r"(a[3]), "r"(b[0]), "r"(b[1]));
}

// ---------------- pack-index machinery ----------------
__global__ void count_kernel(const int* __restrict__ lengths) {
    int t = blockIdx.x, b = threadIdx.x;
    int pred = lengths[b] > t;
    unsigned m = __ballot_sync(0xffffffffu, pred);
    int lane = b & 31, w = b >> 5;
    __shared__ int ws[4];
    if (lane == 0) ws[w] = __popc(m);
    __syncthreads();
    int prefix = 0;
#pragma unroll
    for (int i = 0; i < 4; i++) if (i < w) prefix += ws[i];
    g_local[t * B_ + b] = prefix + __popc(m & ((1u << lane) - 1u));
    if (b == 0) {
        int tot = 0;
#pragma unroll
        for (int i = 0; i < 4; i++) tot += ws[i];
        g_nt[t] = tot;
    }
}

__global__ void offset_kernel() {
    int o = 0;
    for (int t = 0; t < T_; t++) { g_off[t] = o; o += g_nt[t]; }
    g_off[T_] = o;
}

__global__ void scatter_kernel(const int* __restrict__ lengths) {
    int idx = blockIdx.x * 256 + threadIdx.x;
    if (idx >= T_ * B_) return;
    int t = idx >> 7, b = idx & 127;
    if (lengths[b] > t) g_rowmap[g_off[t] + g_local[idx]] = idx;
}

// ---------------- GEMM 1 (fp32 SIMT, proven): Gx = [feat|embed] @ w_ih^T + bias ----------------
__global__ void gx_gemm(const float* __restrict__ features,
                        const int*   __restrict__ captions,
                        const float* __restrict__ embed_w,
                        const float* __restrict__ w_ih,
                        const float* __restrict__ b_ih,
                        const float* __restrict__ b_hh) {
    __shared__ float As[16][64];
    __shared__ float Bs[16][64];
    int tid = threadIdx.x;
    int cn0 = blockIdx.x * 64;
    int rm0 = blockIdx.y * 64;
    int arow = tid >> 2, ac4 = (tid & 3) * 4;

    int r = rm0 + arow;
    int t = r >> 7, b = r & 127;
    const float* aptr;
    if (t == 0) aptr = features + (size_t)b * E_ + ac4;
    else        aptr = embed_w + (size_t)captions[b * T_ + (t - 1)] * E_ + ac4;
    const float* bptr = w_ih + (size_t)(cn0 + arow) * E_ + ac4;

    float acc[4][4] = {};
    int tm = tid >> 4, tn = tid & 15;

    for (int k0 = 0; k0 < E_; k0 += 16) {
        float4 a = *(const float4*)(aptr + k0);
        float4 bb = *(const float4*)(bptr + k0);
        As[ac4 + 0][arow] = a.x;  As[ac4 + 1][arow] = a.y;
        As[ac4 + 2][arow] = a.z;  As[ac4 + 3][arow] = a.w;
        Bs[ac4 + 0][arow] = bb.x; Bs[ac4 + 1][arow] = bb.y;
        Bs[ac4 + 2][arow] = bb.z; Bs[ac4 + 3][arow] = bb.w;
        __syncthreads();
#pragma unroll
        for (int kk = 0; kk < 16; kk++) {
            float4 av = *(const float4*)&As[kk][tm * 4];
            float4 bv = *(const float4*)&Bs[kk][tn * 4];
            float aa[4] = {av.x, av.y, av.z, av.w};
            float bvv[4] = {bv.x, bv.y, bv.z, bv.w};
#pragma unroll
            for (int i = 0; i < 4; i++)
#pragma unroll
                for (int j = 0; j < 4; j++) acc[i][j] += aa[i] * bvv[j];
        }
        __syncthreads();
    }

    int n = cn0 + tn * 4;
    float bias0 = b_ih[n + 0] + b_hh[n + 0];
    float bias1 = b_ih[n + 1] + b_hh[n + 1];
    float bias2 = b_ih[n + 2] + b_hh[n + 2];
    float bias3 = b_ih[n + 3] + b_hh[n + 3];
#pragma unroll
    for (int i = 0; i < 4; i++) {
        int rr = rm0 + tm * 4 + i;
        float4 o;
        o.x = acc[i][0] + bias0; o.y = acc[i][1] + bias1;
        o.z = acc[i][2] + bias2; o.w = acc[i][3] + bias3;
        *(float4*)&g_Gx[(size_t)rr * G4H + n] = o;
    }
}

// ---------------- converters (device globals referenced IN-KERNEL only) ----------------
__global__ void convert_whh(const float* __restrict__ w_hh) {
    int idx = blockIdx.x * 256 + threadIdx.x;   // 2048*512
    int n = idx >> 9, k = idx & 511;
    float v = w_hh[(size_t)n * 512 + k];
    __half hi = __float2half(v);
    __half lo = __float2half(v - __half2float(hi));
    size_t base = (size_t)n * K3_ + k;
    g_Whh[base] = hi; g_Whh[base + 512] = hi; g_Whh[base + 1024] = lo;
}

__global__ void init_h2(const float* __restrict__ h0) {
    int idx = blockIdx.x * 256 + threadIdx.x;   // 128*512
    int b = idx >> 9, k = idx & 511;
    float v = h0[idx];
    __half hi = __float2half(v);
    __half lo = __float2half(v - __half2float(hi));
    size_t base = (size_t)b * K3_ + k;
    g_h2[0][base] = hi; g_h2[0][base + 512] = lo; g_h2[0][base + 1024] = hi;
}

__global__ void convert_Bout(const float* __restrict__ lin_w) {
    int idx = blockIdx.x * 256 + threadIdx.x;   // 32000*512
    g_Bh[idx] = __float2half(lin_w[idx]);
}

__global__ void convert_Aout() {
    int idx = blockIdx.x * 256 + threadIdx.x;   // 1664*512
    int m = idx >> 9;
    int nr = g_off[T_];
    int src = (m < nr) ? g_rowmap[m] : 0;
    g_Ah[idx] = __float2half(g_hs[(size_t)src * 512 + (idx & 511)]);
}

// ---------------- shared template constants ----------------
#define RS_      144
#define STAGE_   36864

// ---------------- recurrence GEMM (clone of proven out_gemm_mma) ----------------
// part[split][n][b] = sum_{k in split} Whh''[n,k] * h''[b,k]
__global__ void __launch_bounds__(256, 1) rec_gemm(int t) {
    extern __shared__ char smem[];
    uint32_t sb = smem_u32(smem);
    int tid = threadIdx.x, lane = tid & 31, wid = tid >> 5;
    int split = blockIdx.x;
    int m0 = blockIdx.y * 128;
    const __half* hin = g_h2[t & 1];
    int wm = (wid >> 2) * 64, wn = (wid & 3) * 32;

    float acc[4][4][4] = {};

#define REC_LOAD(s, kc) do { \
        uint32_t base_ = sb + (s) * STAGE_; \
        int k0_ = (split * 3 + (kc)) * 64; \
        for (int i = tid; i < 1024; i += 256) { \
            int r_ = i >> 3, c_ = i & 7; \
            cp_async16(base_ + r_ * RS_ + c_ * 16, \
                       g_Whh + (size_t)(m0 + r_) * K3_ + k0_ + c_ * 8); \
            cp_async16(base_ + 18432 + r_ * RS_ + c_ * 16, \
                       hin + (size_t)r_ * K3_ + k0_ + c_ * 8); \
        } \
        asm volatile("cp.async.commit_group;" ::: "memory"); \
    } while (0)

    REC_LOAD(0, 0);
    REC_LOAD(1, 1);

    for (int kc = 0; kc < 3; kc++) {
        asm volatile("cp.async.wait_group 1;" ::: "memory");
        __syncthreads();
        int s = kc & 1;
        uint32_t sA = sb + s * STAGE_;
        uint32_t sB = sA + 18432;
        uint32_t aA = sA + (uint32_t)(wm + (lane & 15)) * RS_ + ((lane >> 4) << 4);
        uint32_t aB = sB + (uint32_t)(wn + (lane & 7) + ((lane & 16) >> 1)) * RS_ + ((lane & 8) << 1);
#pragma unroll
        for (int st = 0; st < 4; st++) {
            uint32_t af[4][4], bfr[2][4];
#pragma unroll
            for (int ta = 0; ta < 4; ta++) ldsm_x4(af[ta], aA + ta * (16 * RS_) + st * 32);
#pragma unroll
            for (int tb = 0; tb < 2; tb++) ldsm_x4(bfr[tb], aB + tb * (16 * RS_) + st * 32);
#pragma unroll
            for (int ta = 0; ta < 4; ta++)
#pragma unroll
                for (int tn = 0; tn < 4; tn++)
                    mma_fp16(acc[ta][tn], af[ta], &bfr[tn >> 1][(tn & 1) * 2]);
        }
        __syncthreads();
        if (kc + 2 < 3) REC_LOAD(s, kc + 2);
        else asm volatile("cp.async.commit_group;" ::: "memory");
    }
#undef REC_LOAD

    float* part = g_part + (size_t)split * G4H * B_;
    int g = lane >> 2, tc2 = (lane & 3) * 2;
#pragma unroll
    for (int ta = 0; ta < 4; ta++) {
        int j0 = m0 + wm + ta * 16 + g;
        int j1 = j0 + 8;
#pragma unroll
        for (int tn = 0; tn < 4; tn++) {
            int col = wn + tn * 8 + tc2;
            float2 o0 = {acc[ta][tn][0], acc[ta][tn][1]};
            float2 o1 = {acc[ta][tn][2], acc[ta][tn][3]};
            *(float2*)&part[(size_t)j0 * B_ + col] = o0;
            *(float2*)&part[(size_t)j1 * B_ + col] = o1;
        }
    }
}

// ---------------- cell + split reduce + h'' emit ----------------
__device__ __forceinline__ float sigmoidf_(float x) { return 1.0f / (1.0f + expf(-x)); }

__global__ void cell_reduce(int t, const float* __restrict__ c0) {
    int idx = blockIdx.x * 256 + threadIdx.x;   // 65536
    int b = idx & 127, j = idx >> 7;            // b fast -> part reads coalesced
    const float* gxr = g_Gx + (size_t)(t * B_ + b) * G4H;
    __half* hout = g_h2[(t + 1) & 1];

    float gate[4];
#pragma unroll
    for (int g = 0; g < 4; g++) {
        float s = gxr[g * 512 + j];
        size_t off = (size_t)(g * 512 + j) * B_ + b;
#pragma unroll
        for (int sp = 0; sp < NSPLIT; sp++)
            s += g_part[(size_t)sp * G4H * B_ + off];
        gate[g] = s;
    }
    float cp = (t == 0) ? c0[b * 512 + j] : g_c[j * 128 + b];
    float cn = sigmoidf_(gate[1]) * cp + sigmoidf_(gate[0]) * tanhf(gate[2]);
    float h = sigmoidf_(gate[3]) * tanhf(cn);
    g_c[j * 128 + b] = cn;
    g_hs[(size_t)t * B_ * H_ + b * 512 + j] = h;
    __half hh = __float2half(h);
    __half hl = __float2half(h - __half2float(hh));
    size_t hb = (size_t)b * K3_ + j;
    hout[hb] = hh; hout[hb + 512] = hl; hout[hb + 1024] = hh;
}

// ---------------- GEMM 3 (mma.sync fp16, K=512, proven): out = Ah @ Bh^T + lin_b ----------------
#define NCHUNK_  8

__global__ void __launch_bounds__(256, 1) out_gemm_mma(const float* __restrict__ lin_b,
                                                       float* __restrict__ out, int nrows) {
    extern __shared__ char smem[];
    uint32_t sb = smem_u32(smem);
    int tid = threadIdx.x, lane = tid & 31, wid = tid >> 5;
    int n0 = blockIdx.x * 128, m0 = blockIdx.y * 128;
    int wm = (wid >> 2) * 64, wn = (wid & 3) * 32;

    float acc[4][4][4] = {};

#define LOAD_STAGE(s, kc) do { \
        uint32_t base_ = sb + (s) * STAGE_; \
        int k0_ = (kc) * 64; \
        for (int i = tid; i < 1024; i += 256) { \
            int r_ = i >> 3, c_ = i & 7; \
            cp_async16(base_ + r_ * RS_ + c_ * 16, \
                       g_Ah + (size_t)(m0 + r_) * 512 + k0_ + c_ * 8); \
            cp_async16(base_ + 18432 + r_ * RS_ + c_ * 16, \
                       g_Bh + (size_t)(n0 + r_) * 512 + k0_ + c_ * 8); \
        } \
        asm volatile("cp.async.commit_group;" ::: "memory"); \
    } while (0)

    LOAD_STAGE(0, 0);
    LOAD_STAGE(1, 1);

    for (int kc = 0; kc < NCHUNK_; kc++) {
        asm volatile("cp.async.wait_group 1;" ::: "memory");
        __syncthreads();
        int s = kc & 1;
        uint32_t sA = sb + s * STAGE_;
        uint32_t sB = sA + 18432;
        uint32_t aA = sA + (uint32_t)(wm + (lane & 15)) * RS_ + ((lane >> 4) << 4);
        uint32_t aB = sB + (uint32_t)(wn + (lane & 7) + ((lane & 16) >> 1)) * RS_ + ((lane & 8) << 1);
#pragma unroll
        for (int st = 0; st < 4; st++) {
            uint32_t af[4][4], bfr[2][4];
#pragma unroll
            for (int ta = 0; ta < 4; ta++) ldsm_x4(af[ta], aA + ta * (16 * RS_) + st * 32);
#pragma unroll
            for (int tb = 0; tb < 2; tb++) ldsm_x4(bfr[tb], aB + tb * (16 * RS_) + st * 32);
#pragma unroll
            for (int ta = 0; ta < 4; ta++)
#pragma unroll
                for (int tn = 0; tn < 4; tn++)
                    mma_fp16(acc[ta][tn], af[ta], &bfr[tn >> 1][(tn & 1) * 2]);
        }
        __syncthreads();
        if (kc + 2 < NCHUNK_) {
            LOAD_STAGE(s, kc + 2);
        } else {
            asm volatile("cp.async.commit_group;" ::: "memory");
        }
    }
#undef LOAD_STAGE

    int g = lane >> 2, tc2 = (lane & 3) * 2;
#pragma unroll
    for (int ta = 0; ta < 4; ta++) {
        int j0 = m0 + wm + ta * 16 + g;
        int j1 = j0 + 8;
#pragma unroll
        for (int tn = 0; tn < 4; tn++) {
            int col = n0 + wn + tn * 8 + tc2;
            float2 lb = *(const float2*)&lin_b[col];
            if (j0 < nrows) {
                float2 o = {acc[ta][tn][0] + lb.x, acc[ta][tn][1] + lb.y};
                *(float2*)&out[(size_t)j0 * V_ + col] = o;
            }
            if (j1 < nrows) {
                float2 o = {acc[ta][tn][2] + lb.x, acc[ta][tn][3] + lb.y};
                *(float2*)&out[(size_t)j1 * V_ + col] = o;
            }
        }
    }
}

// ---------------- launch ----------------
extern "C" void kernel_launch(void* const* d_in, const int* in_sizes, int n_in,
                              void* d_out, int out_size) {
    const float* features = (const float*)d_in[0];
    const int*   captions = (const int*)d_in[1];
    const int*   lengths  = (const int*)d_in[2];
    const float* h0       = (const float*)d_in[3];
    const float* c0       = (const float*)d_in[4];
    const float* embed_w  = (const float*)d_in[5];
    const float* w_ih     = (const float*)d_in[6];
    const float* w_hh     = (const float*)d_in[7];
    const float* b_ih     = (const float*)d_in[8];
    const float* b_hh     = (const float*)d_in[9];
    const float* lin_w    = (const float*)d_in[10];
    const float* lin_b    = (const float*)d_in[11];
    float* out = (float*)d_out;
    int nrows = out_size / V_;

    cudaFuncSetAttribute(out_gemm_mma, cudaFuncAttributeMaxDynamicSharedMemorySize,
                         2 * STAGE_);
    cudaFuncSetAttribute(rec_gemm, cudaFuncAttributeMaxDynamicSharedMemorySize,
                         2 * STAGE_);

    // pack indices
    count_kernel<<<T_, 128>>>(lengths);
    offset_kernel<<<1, 1>>>();
    scatter_kernel<<<(T_ * B_ + 255) / 256, 256>>>(lengths);

    // operand builds (all device-global writes happen INSIDE kernels)
    convert_Bout<<<(V_ * 512) / 256, 256>>>(lin_w);
    convert_whh<<<(G4H * 512) / 256, 256>>>(w_hh);
    init_h2<<<(B_ * 512) / 256, 256>>>(h0);

    // input projection for all timesteps at once (fp32, proven)
    gx_gemm<<<dim3(G4H / 64, (T_ * B_) / 64), 256>>>(features, captions, embed_w,
                                                     w_ih, b_ih, b_hh);

    // recurrence: split-K tensor-core GEMM (proven template) + reduce/cell per step
    for (int t = 0; t < T_; t++) {
        rec_gemm<<<dim3(NSPLIT, G4H / 128), 256, 2 * STAGE_>>>(t);
        cell_reduce<<<(B_ * H_) / 256, 256>>>(t, c0);
    }

    // A operand build (packed-row gather)
    convert_Aout<<<(1664 * 512) / 256, 256>>>();

    // tensor-core packed logits (single fp16, proven)
    int mtiles = (nrows + 127) / 128;   // 13
    out_gemm_mma<<<dim3(V_ / 128, mtiles), 256, 2 * STAGE_>>>(lin_b, out, nrows);
}

// round 10
// speedup vs baseline: 4.1665x; 1.1970x over previous
#include <cuda_runtime.h>
#include <cuda_fp16.h>
#include <math.h>
#include <cstdint>

#define B_   128
#define T_   20
#define E_   512
#define H_   512
#define V_   32000
#define G4H  2048   // 4*H
#define K3_  1536   // 3-term split-extended K
#define NSPLIT 8

// ---------------- scratch (static device globals; IN-KERNEL access only) ----------------
__device__ float g_Gx[T_ * B_ * G4H];   // x_t @ w_ih^T + bias, all steps
__device__ float g_hs[T_ * B_ * H_];    // all hidden states (time-major)
__device__ float g_c[B_ * H_];          // cell state ([j*128+b] layout)
__device__ float g_part[NSPLIT * G4H * B_];  // split-K partials [split][n][b]
__device__ int   g_nt[T_];
__device__ int   g_off[T_ + 1];
__device__ int   g_local[T_ * B_];
__device__ int   g_rowmap[T_ * B_];     // packed row j -> t*B+b

// fp16 3-term operands
__device__ __align__(16) __half g_X2[2560u * K3_];     // [xhi|xlo|xhi]
__device__ __align__(16) __half g_Wih[G4H * K3_];      // [whi|whi|wlo]
__device__ __align__(16) __half g_Whh[G4H * K3_];      // [whi|whi|wlo]
__device__ __align__(16) __half g_h2[2][B_ * K3_];     // ping-pong [hhi|hlo|hhi]
// out-GEMM single-fp16 operands
__device__ __align__(16) __half g_Ah[1664u * 512u];    // packed h rows
__device__ __align__(16) __half g_Bh[32000u * 512u];   // lin_w rows

// ---------------- PTX helpers (sm_80-level; legal on plain sm_103 target) ----------------
__device__ __forceinline__ uint32_t smem_u32(const void* p) {
    uint32_t a;
    asm("{ .reg .u64 t; cvta.to.shared.u64 t, %1; cvt.u32.u64 %0, t; }" : "=r"(a) : "l"(p));
    return a;
}
__device__ __forceinline__ void cp_async16(uint32_t saddr, const void* g) {
    asm volatile("cp.async.cg.shared.global [%0], [%1], 16;" :: "r"(saddr), "l"(g));
}
__device__ __forceinline__ void ldsm_x4(uint32_t* r, uint32_t addr) {
    asm volatile("ldmatrix.sync.aligned.m8n8.x4.shared.b16 {%0,%1,%2,%3}, [%4];"
        : "=r"(r[0]), "=r"(r[1]), "=r"(r[2]), "=r"(r[3]) : "r"(addr));
}
__device__ __forceinline__ void mma_fp16(float* d, const uint32_t* a, const uint32_t* b) {
    asm volatile("mma.sync.aligned.m16n8k16.row.col.f32.f16.f16.f32 "
        "{%0,%1,%2,%3}, {%4,%5,%6,%7}, {%8,%9}, {%0,%1,%2,%3};"
        : "+f"(d[0]), "+f"(d[1]), "+f"(d[2]), "+f"(d[3])
        : "r"(a[0]), "r"(a[1]), "r"(a[2]), "r"(a[3]), "r"(b[0]), "r"(b[1]));
}

// ---------------- pack-index machinery ----------------
__global__ void count_kernel(const int* __restrict__ lengths) {
    int t = blockIdx.x, b = threadIdx.x;
    int pred = lengths[b] > t;
    unsigned m = __ballot_sync(0xffffffffu, pred);
    int lane = b & 31, w = b >> 5;
    __shared__ int ws[4];
    if (lane == 0) ws[w] = __popc(m);
    __syncthreads();
    int prefix = 0;
#pragma unroll
    for (int i = 0; i < 4; i++) if (i < w) prefix += ws[i];
    g_local[t * B_ + b] = prefix + __popc(m & ((1u << lane) - 1u));
    if (b == 0) {
        int tot = 0;
#pragma unroll
        for (int i = 0; i < 4; i++) tot += ws[i];
        g_nt[t] = tot;
    }
}

__global__ void offset_kernel() {
    int o = 0;
    for (int t = 0; t < T_; t++) { g_off[t] = o; o += g_nt[t]; }
    g_off[T_] = o;
}

__global__ void scatter_kernel(const int* __restrict__ lengths) {
    int idx = blockIdx.x * 256 + threadIdx.x;
    if (idx >= T_ * B_) return;
    int t = idx >> 7, b = idx & 127;
    if (lengths[b] > t) g_rowmap[g_off[t] + g_local[idx]] = idx;
}

// ---------------- converters (device globals referenced IN-KERNEL only) ----------------
__global__ void convert_wih(const float* __restrict__ w_ih) {
    int idx = blockIdx.x * 256 + threadIdx.x;   // 2048*512
    int n = idx >> 9, k = idx & 511;
    float v = w_ih[(size_t)n * 512 + k];
    __half hi = __float2half(v);
    __half lo = __float2half(v - __half2float(hi));
    size_t base = (size_t)n * K3_ + k;
    g_Wih[base] = hi; g_Wih[base + 512] = hi; g_Wih[base + 1024] = lo;
}

__global__ void convert_whh(const float* __restrict__ w_hh) {
    int idx = blockIdx.x * 256 + threadIdx.x;   // 2048*512
    int n = idx >> 9, k = idx & 511;
    float v = w_hh[(size_t)n * 512 + k];
    __half hi = __float2half(v);
    __half lo = __float2half(v - __half2float(hi));
    size_t base = (size_t)n * K3_ + k;
    g_Whh[base] = hi; g_Whh[base + 512] = hi; g_Whh[base + 1024] = lo;
}

// X'' rows: [xhi | xlo | xhi]; row r: t=r>>7, b=r&127
__global__ void convert_x2(const float* __restrict__ features,
                           const int*   __restrict__ captions,
                           const float* __restrict__ embed_w) {
    int idx = blockIdx.x * 256 + threadIdx.x;   // 2560*512
    int r = idx >> 9, k = idx & 511;
    int t = r >> 7, b = r & 127;
    float v;
    if (t == 0) v = features[(size_t)b * E_ + k];
    else        v = embed_w[(size_t)captions[b * T_ + (t - 1)] * E_ + k];
    __half hi = __float2half(v);
    __half lo = __float2half(v - __half2float(hi));
    size_t base = (size_t)r * K3_ + k;
    g_X2[base] = hi; g_X2[base + 512] = lo; g_X2[base + 1024] = hi;
}

__global__ void init_h2(const float* __restrict__ h0) {
    int idx = blockIdx.x * 256 + threadIdx.x;   // 128*512
    int b = idx >> 9, k = idx & 511;
    float v = h0[idx];
    __half hi = __float2half(v);
    __half lo = __float2half(v - __half2float(hi));
    size_t base = (size_t)b * K3_ + k;
    g_h2[0][base] = hi; g_h2[0][base + 512] = lo; g_h2[0][base + 1024] = hi;
}

// vectorized: 8 fp32 in -> 8 fp16 out per thread
__global__ void convert_Bout(const float4* __restrict__ lin_w4) {
    int idx = blockIdx.x * 256 + threadIdx.x;   // (32000*512)/8 = 2048000
    float4 a = lin_w4[2 * idx], b = lin_w4[2 * idx + 1];
    __half2 h0 = __floats2half2_rn(a.x, a.y);
    __half2 h1 = __floats2half2_rn(a.z, a.w);
    __half2 h2 = __floats2half2_rn(b.x, b.y);
    __half2 h3 = __floats2half2_rn(b.z, b.w);
    uint4 o = {*(uint32_t*)&h0, *(uint32_t*)&h1, *(uint32_t*)&h2, *(uint32_t*)&h3};
    ((uint4*)g_Bh)[idx] = o;
}

__global__ void convert_Aout() {
    int idx = blockIdx.x * 256 + threadIdx.x;   // 1664*512
    int m = idx >> 9;
    int nr = g_off[T_];
    int src = (m < nr) ? g_rowmap[m] : 0;
    g_Ah[idx] = __float2half(g_hs[(size_t)src * 512 + (idx & 511)]);
}

// ---------------- shared template constants ----------------
#define RS_      144
#define STAGE_   36864

// ---------------- gx GEMM (proven template, fp16 3-term): g_Gx = X''@Wih''^T + bias ----------------
__global__ void __launch_bounds__(256, 1) gx_mma(const float* __restrict__ b_ih,
                                                 const float* __restrict__ b_hh) {
    extern __shared__ char smem[];
    uint32_t sb = smem_u32(smem);
    int tid = threadIdx.x, lane = tid & 31, wid = tid >> 5;
    int n0 = blockIdx.x * 128, m0 = blockIdx.y * 128;
    int wm = (wid >> 2) * 64, wn = (wid & 3) * 32;
    float acc[4][4][4] = {};

#define GX_LOAD(s, kc) do { \
        uint32_t base_ = sb + (s) * STAGE_; \
        int k0_ = (kc) * 64; \
        for (int i = tid; i < 1024; i += 256) { \
            int r_ = i >> 3, c_ = i & 7; \
            cp_async16(base_ + r_ * RS_ + c_ * 16, \
                       g_X2 + (size_t)(m0 + r_) * K3_ + k0_ + c_ * 8); \
            cp_async16(base_ + 18432 + r_ * RS_ + c_ * 16, \
                       g_Wih + (size_t)(n0 + r_) * K3_ + k0_ + c_ * 8); \
        } \
        asm volatile("cp.async.commit_group;" ::: "memory"); \
    } while (0)

    GX_LOAD(0, 0);
    GX_LOAD(1, 1);
    for (int kc = 0; kc < 24; kc++) {
        asm volatile("cp.async.wait_group 1;" ::: "memory");
        __syncthreads();
        int s = kc & 1;
        uint32_t sA = sb + s * STAGE_;
        uint32_t sB = sA + 18432;
        uint32_t aA = sA + (uint32_t)(wm + (lane & 15)) * RS_ + ((lane >> 4) << 4);
        uint32_t aB = sB + (uint32_t)(wn + (lane & 7) + ((lane & 16) >> 1)) * RS_ + ((lane & 8) << 1);
#pragma unroll
        for (int st = 0; st < 4; st++) {
            uint32_t af[4][4], bfr[2][4];
#pragma unroll
            for (int ta = 0; ta < 4; ta++) ldsm_x4(af[ta], aA + ta * (16 * RS_) + st * 32);
#pragma unroll
            for (int tb = 0; tb < 2; tb++) ldsm_x4(bfr[tb], aB + tb * (16 * RS_) + st * 32);
#pragma unroll
            for (int ta = 0; ta < 4; ta++)
#pragma unroll
                for (int tn = 0; tn < 4; tn++)
                    mma_fp16(acc[ta][tn], af[ta], &bfr[tn >> 1][(tn & 1) * 2]);
        }
        __syncthreads();
        if (kc + 2 < 24) GX_LOAD(s, kc + 2);
        else asm volatile("cp.async.commit_group;" ::: "memory");
    }
#undef GX_LOAD

    int g = lane >> 2, tc2 = (lane & 3) * 2;
#pragma unroll
    for (int ta = 0; ta < 4; ta++) {
        int j0 = m0 + wm + ta * 16 + g;
#pragma unroll
        for (int tn = 0; tn < 4; tn++) {
            int col = n0 + wn + tn * 8 + tc2;
            float2 bi = {b_ih[col] + b_hh[col], b_ih[col + 1] + b_hh[col + 1]};
            float2 o0 = {acc[ta][tn][0] + bi.x, acc[ta][tn][1] + bi.y};
            float2 o1 = {acc[ta][tn][2] + bi.x, acc[ta][tn][3] + bi.y};
            *(float2*)&g_Gx[(size_t)j0 * G4H + col] = o0;
            *(float2*)&g_Gx[(size_t)(j0 + 8) * G4H + col] = o1;
        }
    }
}

// ---------------- recurrence GEMM (proven) ----------------
__global__ void __launch_bounds__(256, 1) rec_gemm(int t) {
    extern __shared__ char smem[];
    uint32_t sb = smem_u32(smem);
    int tid = threadIdx.x, lane = tid & 31, wid = tid >> 5;
    int split = blockIdx.x;
    int m0 = blockIdx.y * 128;
    const __half* hin = g_h2[t & 1];
    int wm = (wid >> 2) * 64, wn = (wid & 3) * 32;

    float acc[4][4][4] = {};

#define REC_LOAD(s, kc) do { \
        uint32_t base_ = sb + (s) * STAGE_; \
        int k0_ = (split * 3 + (kc)) * 64; \
        for (int i = tid; i < 1024; i += 256) { \
            int r_ = i >> 3, c_ = i & 7; \
            cp_async16(base_ + r_ * RS_ + c_ * 16, \
                       g_Whh + (size_t)(m0 + r_) * K3_ + k0_ + c_ * 8); \
            cp_async16(base_ + 18432 + r_ * RS_ + c_ * 16, \
                       hin + (size_t)r_ * K3_ + k0_ + c_ * 8); \
        } \
        asm volatile("cp.async.commit_group;" ::: "memory"); \
    } while (0)

    REC_LOAD(0, 0);
    REC_LOAD(1, 1);

    for (int kc = 0; kc < 3; kc++) {
        asm volatile("cp.async.wait_group 1;" ::: "memory");
        __syncthreads();
        int s = kc & 1;
        uint32_t sA = sb + s * STAGE_;
        uint32_t sB = sA + 18432;
        uint32_t aA = sA + (uint32_t)(wm + (lane & 15)) * RS_ + ((lane >> 4) << 4);
        uint32_t aB = sB + (uint32_t)(wn + (lane & 7) + ((lane & 16) >> 1)) * RS_ + ((lane & 8) << 1);
#pragma unroll
        for (int st = 0; st < 4; st++) {
            uint32_t af[4][4], bfr[2][4];
#pragma unroll
            for (int ta = 0; ta < 4; ta++) ldsm_x4(af[ta], aA + ta * (16 * RS_) + st * 32);
#pragma unroll
            for (int tb = 0; tb < 2; tb++) ldsm_x4(bfr[tb], aB + tb * (16 * RS_) + st * 32);
#pragma unroll
            for (int ta = 0; ta < 4; ta++)
#pragma unroll
                for (int tn = 0; tn < 4; tn++)
                    mma_fp16(acc[ta][tn], af[ta], &bfr[tn >> 1][(tn & 1) * 2]);
        }
        __syncthreads();
        if (kc + 2 < 3) REC_LOAD(s, kc + 2);
        else asm volatile("cp.async.commit_group;" ::: "memory");
    }
#undef REC_LOAD

    float* part = g_part + (size_t)split * G4H * B_;
    int g = lane >> 2, tc2 = (lane & 3) * 2;
#pragma unroll
    for (int ta = 0; ta < 4; ta++) {
        int j0 = m0 + wm + ta * 16 + g;
        int j1 = j0 + 8;
#pragma unroll
        for (int tn = 0; tn < 4; tn++) {
            int col = wn + tn * 8 + tc2;
            float2 o0 = {acc[ta][tn][0], acc[ta][tn][1]};
            float2 o1 = {acc[ta][tn][2], acc[ta][tn][3]};
            *(float2*)&part[(size_t)j0 * B_ + col] = o0;
            *(float2*)&part[(size_t)j1 * B_ + col] = o1;
        }
    }
}

// ---------------- cell + split reduce + h'' emit (proven) ----------------
__device__ __forceinline__ float sigmoidf_(float x) { return 1.0f / (1.0f + expf(-x)); }

__global__ void cell_reduce(int t, const float* __restrict__ c0) {
    int idx = blockIdx.x * 256 + threadIdx.x;   // 65536
    int b = idx & 127, j = idx >> 7;
    const float* gxr = g_Gx + (size_t)(t * B_ + b) * G4H;
    __half* hout = g_h2[(t + 1) & 1];

    float gate[4];
#pragma unroll
    for (int g = 0; g < 4; g++) {
        float s = gxr[g * 512 + j];
        size_t off = (size_t)(g * 512 + j) * B_ + b;
#pragma unroll
        for (int sp = 0; sp < NSPLIT; sp++)
            s += g_part[(size_t)sp * G4H * B_ + off];
        gate[g] = s;
    }
    float cp = (t == 0) ? c0[b * 512 + j] : g_c[j * 128 + b];
    float cn = sigmoidf_(gate[1]) * cp + sigmoidf_(gate[0]) * tanhf(gate[2]);
    float h = sigmoidf_(gate[3]) * tanhf(cn);
    g_c[j * 128 + b] = cn;
    g_hs[(size_t)t * B_ * H_ + b * 512 + j] = h;
    __half hh = __float2half(h);
    __half hl = __float2half(h - __half2float(hh));
    size_t hb = (size_t)b * K3_ + j;
    hout[hb] = hh; hout[hb + 512] = hl; hout[hb + 1024] = hh;
}

// ---------------- GEMM 3 (mma.sync fp16, K=512, proven): out = Ah @ Bh^T + lin_b ----------------
#define NCHUNK_  8

__global__ void __launch_bounds__(256, 1) out_gemm_mma(const float* __restrict__ lin_b,
                                                       float* __restrict__ out, int nrows) {
    extern __shared__ char smem[];
    uint32_t sb = smem_u32(smem);
    int tid = threadIdx.x, lane = tid & 31, wid = tid >> 5;
    int n0 = blockIdx.x * 128, m0 = blockIdx.y * 128;
    int wm = (wid >> 2) * 64, wn = (wid & 3) * 32;

    float acc[4][4][4] = {};

#define LOAD_STAGE(s, kc) do { \
        uint32_t base_ = sb + (s) * STAGE_; \
        int k0_ = (kc) * 64; \
        for (int i = tid; i < 1024; i += 256) { \
            int r_ = i >> 3, c_ = i & 7; \
            cp_async16(base_ + r_ * RS_ + c_ * 16, \
                       g_Ah + (size_t)(m0 + r_) * 512 + k0_ + c_ * 8); \
            cp_async16(base_ + 18432 + r_ * RS_ + c_ * 16, \
                       g_Bh + (size_t)(n0 + r_) * 512 + k0_ + c_ * 8); \
        } \
        asm volatile("cp.async.commit_group;" ::: "memory"); \
    } while (0)

    LOAD_STAGE(0, 0);
    LOAD_STAGE(1, 1);

    for (int kc = 0; kc < NCHUNK_; kc++) {
        asm volatile("cp.async.wait_group 1;" ::: "memory");
        __syncthreads();
        int s = kc & 1;
        uint32_t sA = sb + s * STAGE_;
        uint32_t sB = sA + 18432;
        uint32_t aA = sA + (uint32_t)(wm + (lane & 15)) * RS_ + ((lane >> 4) << 4);
        uint32_t aB = sB + (uint32_t)(wn + (lane & 7) + ((lane & 16) >> 1)) * RS_ + ((lane & 8) << 1);
#pragma unroll
        for (int st = 0; st < 4; st++) {
            uint32_t af[4][4], bfr[2][4];
#pragma unroll
            for (int ta = 0; ta < 4; ta++) ldsm_x4(af[ta], aA + ta * (16 * RS_) + st * 32);
#pragma unroll
            for (int tb = 0; tb < 2; tb++) ldsm_x4(bfr[tb], aB + tb * (16 * RS_) + st * 32);
#pragma unroll
            for (int ta = 0; ta < 4; ta++)
#pragma unroll
                for (int tn = 0; tn < 4; tn++)
                    mma_fp16(acc[ta][tn], af[ta], &bfr[tn >> 1][(tn & 1) * 2]);
        }
        __syncthreads();
        if (kc + 2 < NCHUNK_) {
            LOAD_STAGE(s, kc + 2);
        } else {
            asm volatile("cp.async.commit_group;" ::: "memory");
        }
    }
#undef LOAD_STAGE

    int g = lane >> 2, tc2 = (lane & 3) * 2;
#pragma unroll
    for (int ta = 0; ta < 4; ta++) {
        int j0 = m0 + wm + ta * 16 + g;
        int j1 = j0 + 8;
#pragma unroll
        for (int tn = 0; tn < 4; tn++) {
            int col = n0 + wn + tn * 8 + tc2;
            float2 lb = *(const float2*)&lin_b[col];
            if (j0 < nrows) {
                float2 o = {acc[ta][tn][0] + lb.x, acc[ta][tn][1] + lb.y};
                *(float2*)&out[(size_t)j0 * V_ + col] = o;
            }
            if (j1 < nrows) {
                float2 o = {acc[ta][tn][2] + lb.x, acc[ta][tn][3] + lb.y};
                *(float2*)&out[(size_t)j1 * V_ + col] = o;
            }
        }
    }
}

// ---------------- launch ----------------
extern "C" void kernel_launch(void* const* d_in, const int* in_sizes, int n_in,
                              void* d_out, int out_size) {
    const float* features = (const float*)d_in[0];
    const int*   captions = (const int*)d_in[1];
    const int*   lengths  = (const int*)d_in[2];
    const float* h0       = (const float*)d_in[3];
    const float* c0       = (const float*)d_in[4];
    const float* embed_w  = (const float*)d_in[5];
    const float* w_ih     = (const float*)d_in[6];
    const float* w_hh     = (const float*)d_in[7];
    const float* b_ih     = (const float*)d_in[8];
    const float* b_hh     = (const float*)d_in[9];
    const float* lin_w    = (const float*)d_in[10];
    const float* lin_b    = (const float*)d_in[11];
    float* out = (float*)d_out;
    int nrows = out_size / V_;

    cudaFuncSetAttribute(out_gemm_mma, cudaFuncAttributeMaxDynamicSharedMemorySize,
                         2 * STAGE_);
    cudaFuncSetAttribute(rec_gemm, cudaFuncAttributeMaxDynamicSharedMemorySize,
                         2 * STAGE_);
    cudaFuncSetAttribute(gx_mma, cudaFuncAttributeMaxDynamicSharedMemorySize,
                         2 * STAGE_);

    // pack indices
    count_kernel<<<T_, 128>>>(lengths);
    offset_kernel<<<1, 1>>>();
    scatter_kernel<<<(T_ * B_ + 255) / 256, 256>>>(lengths);

    // operand builds (device globals written IN-KERNEL only)
    convert_Bout<<<(V_ * 512 / 8) / 256, 256>>>((const float4*)lin_w);
    convert_wih<<<(G4H * 512) / 256, 256>>>(w_ih);
    convert_whh<<<(G4H * 512) / 256, 256>>>(w_hh);
    convert_x2<<<(2560 * 512) / 256, 256>>>(features, captions, embed_w);
    init_h2<<<(B_ * 512) / 256, 256>>>(h0);

    // input projection (tensor core, fp16 3-term)
    gx_mma<<<dim3(G4H / 128, 2560 / 128), 256, 2 * STAGE_>>>(b_ih, b_hh);

    // recurrence: split-K tensor-core GEMM + reduce/cell per step
    for (int t = 0; t < T_; t++) {
        rec_gemm<<<dim3(NSPLIT, G4H / 128), 256, 2 * STAGE_>>>(t);
        cell_reduce<<<(B_ * H_) / 256, 256>>>(t, c0);
    }

    // A operand build (packed-row gather)
    convert_Aout<<<(1664 * 512) / 256, 256>>>();

    // tensor-core packed logits (single fp16)
    int mtiles = (nrows + 127) / 128;   // 13
    out_gemm_mma<<<dim3(V_ / 128, mtiles), 256, 2 * STAGE_>>>(lin_b, out, nrows);
}

// round 11
// speedup vs baseline: 4.2177x; 1.0123x over previous
#include <cuda_runtime.h>
#include <cuda_fp16.h>
#include <math.h>
#include <cstdint>

#define B_   128
#define T_   20
#define E_   512
#define H_   512
#define V_   32000
#define G4H  2048   // 4*H
#define K3_  1536   // 3-term split-extended K
#define NSPLIT 8

// ---------------- scratch (static device globals; IN-KERNEL access only) ----------------
__device__ float g_Gx[T_ * B_ * G4H];
__device__ float g_hs[T_ * B_ * H_];
__device__ float g_c[B_ * H_];
__device__ float g_part[NSPLIT * G4H * B_];
__device__ int   g_nt[T_];
__device__ int   g_off[T_ + 1];
__device__ int   g_local[T_ * B_];
__device__ int   g_rowmap[T_ * B_];

__device__ __align__(16) __half g_X2[2560u * K3_];
__device__ __align__(16) __half g_Wih[G4H * K3_];
__device__ __align__(16) __half g_Whh[G4H * K3_];
__device__ __align__(16) __half g_h2[2][B_ * K3_];
__device__ __align__(16) __half g_Ah[1664u * 512u];
__device__ __align__(16) __half g_Bh[32000u * 512u];

// ---------------- PTX helpers ----------------
__device__ __forceinline__ uint32_t smem_u32(const void* p) {
    uint32_t a;
    asm("{ .reg .u64 t; cvta.to.shared.u64 t, %1; cvt.u32.u64 %0, t; }" : "=r"(a) : "l"(p));
    return a;
}
__device__ __forceinline__ void cp_async16(uint32_t saddr, const void* g) {
    asm volatile("cp.async.cg.shared.global [%0], [%1], 16;" :: "r"(saddr), "l"(g));
}
__device__ __forceinline__ void ldsm_x4(uint32_t* r, uint32_t addr) {
    asm volatile("ldmatrix.sync.aligned.m8n8.x4.shared.b16 {%0,%1,%2,%3}, [%4];"
        : "=r"(r[0]), "=r"(r[1]), "=r"(r[2]), "=r"(r[3]) : "r"(addr));
}
__device__ __forceinline__ void mma_fp16(float* d, const uint32_t* a, const uint32_t* b) {
    asm volatile("mma.sync.aligned.m16n8k16.row.col.f32.f16.f16.f32 "
        "{%0,%1,%2,%3}, {%4,%5,%6,%7}, {%8,%9}, {%0,%1,%2,%3};"
        : "+f"(d[0]), "+f"(d[1]), "+f"(d[2]), "+f"(d[3])
        : "r"(a[0]), "r"(a[1]), "r"(a[2]), "r"(a[3]), "r"(b[0]), "r"(b[1]));
}

// ---------------- pack-index machinery ----------------
__global__ void count_kernel(const int* __restrict__ lengths) {
    int t = blockIdx.x, b = threadIdx.x;
    int pred = lengths[b] > t;
    unsigned m = __ballot_sync(0xffffffffu, pred);
    int lane = b & 31, w = b >> 5;
    __shared__ int ws[4];
    if (lane == 0) ws[w] = __popc(m);
    __syncthreads();
    int prefix = 0;
#pragma unroll
    for (int i = 0; i < 4; i++) if (i < w) prefix += ws[i];
    g_local[t * B_ + b] = prefix + __popc(m & ((1u << lane) - 1u));
    if (b == 0) {
        int tot = 0;
#pragma unroll
        for (int i = 0; i < 4; i++) tot += ws[i];
        g_nt[t] = tot;
    }
}

__global__ void offset_kernel() {
    int o = 0;
    for (int t = 0; t < T_; t++) { g_off[t] = o; o += g_nt[t]; }
    g_off[T_] = o;
}

__global__ void scatter_kernel(const int* __restrict__ lengths) {
    int idx = blockIdx.x * 256 + threadIdx.x;
    if (idx >= T_ * B_) return;
    int t = idx >> 7, b = idx & 127;
    if (lengths[b] > t) g_rowmap[g_off[t] + g_local[idx]] = idx;
}

// ---------------- converters (vectorized; device globals written IN-KERNEL only) ----------------
// [whi | whi | wlo], 2 k-elems per thread
__global__ void convert_wih(const float2* __restrict__ w) {
    int idx = blockIdx.x * 256 + threadIdx.x;   // (2048*512)/2
    int n = idx >> 8, k2 = idx & 255;
    float2 v = w[idx];
    __half2 hi = __floats2half2_rn(v.x, v.y);
    __half2 lo = __floats2half2_rn(v.x - __low2float(hi), v.y - __high2float(hi));
    __half2* base = (__half2*)(g_Wih + (size_t)n * K3_ + 2 * k2);
    base[0] = hi; base[256] = hi; base[512] = lo;
}

__global__ void convert_whh(const float2* __restrict__ w) {
    int idx = blockIdx.x * 256 + threadIdx.x;   // (2048*512)/2
    int n = idx >> 8, k2 = idx & 255;
    float2 v = w[idx];
    __half2 hi = __floats2half2_rn(v.x, v.y);
    __half2 lo = __floats2half2_rn(v.x - __low2float(hi), v.y - __high2float(hi));
    __half2* base = (__half2*)(g_Whh + (size_t)n * K3_ + 2 * k2);
    base[0] = hi; base[256] = hi; base[512] = lo;
}

// X'' rows: [xhi | xlo | xhi]
__global__ void convert_x2(const float* __restrict__ features,
                           const int*   __restrict__ captions,
                           const float* __restrict__ embed_w) {
    int idx = blockIdx.x * 256 + threadIdx.x;   // (2560*512)/2
    int r = idx >> 8, k2 = idx & 255;
    int t = r >> 7, b = r & 127;
    float2 v;
    if (t == 0) v = ((const float2*)features)[b * 256 + k2];
    else        v = ((const float2*)embed_w)[(size_t)captions[b * T_ + (t - 1)] * 256 + k2];
    __half2 hi = __floats2half2_rn(v.x, v.y);
    __half2 lo = __floats2half2_rn(v.x - __low2float(hi), v.y - __high2float(hi));
    __half2* base = (__half2*)(g_X2 + (size_t)r * K3_ + 2 * k2);
    base[0] = hi; base[256] = lo; base[512] = hi;
}

__global__ void init_h2(const float* __restrict__ h0) {
    int idx = blockIdx.x * 256 + threadIdx.x;   // 128*512
    int b = idx >> 9, k = idx & 511;
    float v = h0[idx];
    __half hi = __float2half(v);
    __half lo = __float2half(v - __half2float(hi));
    size_t base = (size_t)b * K3_ + k;
    g_h2[0][base] = hi; g_h2[0][base + 512] = lo; g_h2[0][base + 1024] = hi;
}

__global__ void convert_Bout(const float4* __restrict__ lin_w4) {
    int idx = blockIdx.x * 256 + threadIdx.x;   // (32000*512)/8
    float4 a = lin_w4[2 * idx], b = lin_w4[2 * idx + 1];
    __half2 h0 = __floats2half2_rn(a.x, a.y);
    __half2 h1 = __floats2half2_rn(a.z, a.w);
    __half2 h2 = __floats2half2_rn(b.x, b.y);
    __half2 h3 = __floats2half2_rn(b.z, b.w);
    uint4 o = {*(uint32_t*)&h0, *(uint32_t*)&h1, *(uint32_t*)&h2, *(uint32_t*)&h3};
    ((uint4*)g_Bh)[idx] = o;
}

__global__ void convert_Aout() {
    int idx = blockIdx.x * 256 + threadIdx.x;   // (1664*512)/8
    int m = idx >> 6, k8 = (idx & 63) * 8;
    int nr = g_off[T_];
    int src = (m < nr) ? g_rowmap[m] : 0;
    const float4* p = (const float4*)(g_hs + (size_t)src * 512 + k8);
    float4 a = p[0], b = p[1];
    __half2 h0 = __floats2half2_rn(a.x, a.y);
    __half2 h1 = __floats2half2_rn(a.z, a.w);
    __half2 h2 = __floats2half2_rn(b.x, b.y);
    __half2 h3 = __floats2half2_rn(b.z, b.w);
    uint4 o = {*(uint32_t*)&h0, *(uint32_t*)&h1, *(uint32_t*)&h2, *(uint32_t*)&h3};
    *(uint4*)(g_Ah + (size_t)m * 512 + k8) = o;
}

// ---------------- shared template constants ----------------
#define RS_      144
#define STAGE_   36864

// ---------------- gx GEMM: 3-stage single-sync pipeline ----------------
__global__ void __launch_bounds__(256, 1) gx_mma(const float* __restrict__ b_ih,
                                                 const float* __restrict__ b_hh) {
    extern __shared__ char smem[];
    uint32_t sb = smem_u32(smem);
    int tid = threadIdx.x, lane = tid & 31, wid = tid >> 5;
    int n0 = blockIdx.x * 128, m0 = blockIdx.y * 128;
    int wm = (wid >> 2) * 64, wn = (wid & 3) * 32;
    float acc[4][4][4] = {};

#define GX_LOAD(s, kc) do { \
        uint32_t base_ = sb + (s) * STAGE_; \
        int k0_ = (kc) * 64; \
        for (int i = tid; i < 1024; i += 256) { \
            int r_ = i >> 3, c_ = i & 7; \
            cp_async16(base_ + r_ * RS_ + c_ * 16, \
                       g_X2 + (size_t)(m0 + r_) * K3_ + k0_ + c_ * 8); \
            cp_async16(base_ + 18432 + r_ * RS_ + c_ * 16, \
                       g_Wih + (size_t)(n0 + r_) * K3_ + k0_ + c_ * 8); \
        } \
        asm volatile("cp.async.commit_group;" ::: "memory"); \
    } while (0)

    GX_LOAD(0, 0);
    GX_LOAD(1, 1);
    for (int kc = 0; kc < 24; kc++) {
        asm volatile("cp.async.wait_group 1;" ::: "memory");
        __syncthreads();
        if (kc + 2 < 24) GX_LOAD((kc + 2) % 3, kc + 2);
        else asm volatile("cp.async.commit_group;" ::: "memory");
        int s = kc % 3;
        uint32_t sA = sb + s * STAGE_;
        uint32_t sB = sA + 18432;
        uint32_t aA = sA + (uint32_t)(wm + (lane & 15)) * RS_ + ((lane >> 4) << 4);
        uint32_t aB = sB + (uint32_t)(wn + (lane & 7) + ((lane & 16) >> 1)) * RS_ + ((lane & 8) << 1);
#pragma unroll
        for (int st = 0; st < 4; st++) {
            uint32_t af[4][4], bfr[2][4];
#pragma unroll
            for (int ta = 0; ta < 4; ta++) ldsm_x4(af[ta], aA + ta * (16 * RS_) + st * 32);
#pragma unroll
            for (int tb = 0; tb < 2; tb++) ldsm_x4(bfr[tb], aB + tb * (16 * RS_) + st * 32);
#pragma unroll
            for (int ta = 0; ta < 4; ta++)
#pragma unroll
                for (int tn = 0; tn < 4; tn++)
                    mma_fp16(acc[ta][tn], af[ta], &bfr[tn >> 1][(tn & 1) * 2]);
        }
    }
#undef GX_LOAD

    int g = lane >> 2, tc2 = (lane & 3) * 2;
#pragma unroll
    for (int ta = 0; ta < 4; ta++) {
        int j0 = m0 + wm + ta * 16 + g;
#pragma unroll
        for (int tn = 0; tn < 4; tn++) {
            int col = n0 + wn + tn * 8 + tc2;
            float2 bi = {b_ih[col] + b_hh[col], b_ih[col + 1] + b_hh[col + 1]};
            float2 o0 = {acc[ta][tn][0] + bi.x, acc[ta][tn][1] + bi.y};
            float2 o1 = {acc[ta][tn][2] + bi.x, acc[ta][tn][3] + bi.y};
            *(float2*)&g_Gx[(size_t)j0 * G4H + col] = o0;
            *(float2*)&g_Gx[(size_t)(j0 + 8) * G4H + col] = o1;
        }
    }
}

// ---------------- recurrence GEMM (proven 2-stage, unchanged) ----------------
__global__ void __launch_bounds__(256, 1) rec_gemm(int t) {
    extern __shared__ char smem[];
    uint32_t sb = smem_u32(smem);
    int tid = threadIdx.x, lane = tid & 31, wid = tid >> 5;
    int split = blockIdx.x;
    int m0 = blockIdx.y * 128;
    const __half* hin = g_h2[t & 1];
    int wm = (wid >> 2) * 64, wn = (wid & 3) * 32;

    float acc[4][4][4] = {};

#define REC_LOAD(s, kc) do { \
        uint32_t base_ = sb + (s) * STAGE_; \
        int k0_ = (split * 3 + (kc)) * 64; \
        for (int i = tid; i < 1024; i += 256) { \
            int r_ = i >> 3, c_ = i & 7; \
            cp_async16(base_ + r_ * RS_ + c_ * 16, \
                       g_Whh + (size_t)(m0 + r_) * K3_ + k0_ + c_ * 8); \
            cp_async16(base_ + 18432 + r_ * RS_ + c_ * 16, \
                       hin + (size_t)r_ * K3_ + k0_ + c_ * 8); \
        } \
        asm volatile("cp.async.commit_group;" ::: "memory"); \
    } while (0)

    REC_LOAD(0, 0);
    REC_LOAD(1, 1);

    for (int kc = 0; kc < 3; kc++) {
        asm volatile("cp.async.wait_group 1;" ::: "memory");
        __syncthreads();
        int s = kc & 1;
        uint32_t sA = sb + s * STAGE_;
        uint32_t sB = sA + 18432;
        uint32_t aA = sA + (uint32_t)(wm + (lane & 15)) * RS_ + ((lane >> 4) << 4);
        uint32_t aB = sB + (uint32_t)(wn + (lane & 7) + ((lane & 16) >> 1)) * RS_ + ((lane & 8) << 1);
#pragma unroll
        for (int st = 0; st < 4; st++) {
            uint32_t af[4][4], bfr[2][4];
#pragma unroll
            for (int ta = 0; ta < 4; ta++) ldsm_x4(af[ta], aA + ta * (16 * RS_) + st * 32);
#pragma unroll
            for (int tb = 0; tb < 2; tb++) ldsm_x4(bfr[tb], aB + tb * (16 * RS_) + st * 32);
#pragma unroll
            for (int ta = 0; ta < 4; ta++)
#pragma unroll
                for (int tn = 0; tn < 4; tn++)
                    mma_fp16(acc[ta][tn], af[ta], &bfr[tn >> 1][(tn & 1) * 2]);
        }
        __syncthreads();
        if (kc + 2 < 3) REC_LOAD(s, kc + 2);
        else asm volatile("cp.async.commit_group;" ::: "memory");
    }
#undef REC_LOAD

    float* part = g_part + (size_t)split * G4H * B_;
    int g = lane >> 2, tc2 = (lane & 3) * 2;
#pragma unroll
    for (int ta = 0; ta < 4; ta++) {
        int j0 = m0 + wm + ta * 16 + g;
        int j1 = j0 + 8;
#pragma unroll
        for (int tn = 0; tn < 4; tn++) {
            int col = wn + tn * 8 + tc2;
            float2 o0 = {acc[ta][tn][0], acc[ta][tn][1]};
            float2 o1 = {acc[ta][tn][2], acc[ta][tn][3]};
            *(float2*)&part[(size_t)j0 * B_ + col] = o0;
            *(float2*)&part[(size_t)j1 * B_ + col] = o1;
        }
    }
}

// ---------------- cell + split reduce + h'' emit (proven) ----------------
__device__ __forceinline__ float sigmoidf_(float x) { return 1.0f / (1.0f + expf(-x)); }

__global__ void cell_reduce(int t, const float* __restrict__ c0) {
    int idx = blockIdx.x * 256 + threadIdx.x;
    int b = idx & 127, j = idx >> 7;
    const float* gxr = g_Gx + (size_t)(t * B_ + b) * G4H;
    __half* hout = g_h2[(t + 1) & 1];

    float gate[4];
#pragma unroll
    for (int g = 0; g < 4; g++) {
        float s = gxr[g * 512 + j];
        size_t off = (size_t)(g * 512 + j) * B_ + b;
#pragma unroll
        for (int sp = 0; sp < NSPLIT; sp++)
            s += g_part[(size_t)sp * G4H * B_ + off];
        gate[g] = s;
    }
    float cp = (t == 0) ? c0[b * 512 + j] : g_c[j * 128 + b];
    float cn = sigmoidf_(gate[1]) * cp + sigmoidf_(gate[0]) * tanhf(gate[2]);
    float h = sigmoidf_(gate[3]) * tanhf(cn);
    g_c[j * 128 + b] = cn;
    g_hs[(size_t)t * B_ * H_ + b * 512 + j] = h;
    __half hh = __float2half(h);
    __half hl = __float2half(h - __half2float(hh));
    size_t hb = (size_t)b * K3_ + j;
    hout[hb] = hh; hout[hb + 512] = hl; hout[hb + 1024] = hh;
}

// ---------------- out GEMM: 3-stage single-sync pipeline ----------------
#define NCHUNK_  8

__global__ void __launch_bounds__(256, 1) out_gemm_mma(const float* __restrict__ lin_b,
                                                       float* __restrict__ out, int nrows) {
    extern __shared__ char smem[];
    uint32_t sb = smem_u32(smem);
    int tid = threadIdx.x, lane = tid & 31, wid = tid >> 5;
    int n0 = blockIdx.x * 128, m0 = blockIdx.y * 128;
    int wm = (wid >> 2) * 64, wn = (wid & 3) * 32;

    float acc[4][4][4] = {};

#define LOAD_STAGE(s, kc) do { \
        uint32_t base_ = sb + (s) * STAGE_; \
        int k0_ = (kc) * 64; \
        for (int i = tid; i < 1024; i += 256) { \
            int r_ = i >> 3, c_ = i & 7; \
            cp_async16(base_ + r_ * RS_ + c_ * 16, \
                       g_Ah + (size_t)(m0 + r_) * 512 + k0_ + c_ * 8); \
            cp_async16(base_ + 18432 + r_ * RS_ + c_ * 16, \
                       g_Bh + (size_t)(n0 + r_) * 512 + k0_ + c_ * 8); \
        } \
        asm volatile("cp.async.commit_group;" ::: "memory"); \
    } while (0)

    LOAD_STAGE(0, 0);
    LOAD_STAGE(1, 1);

    for (int kc = 0; kc < NCHUNK_; kc++) {
        asm volatile("cp.async.wait_group 1;" ::: "memory");
        __syncthreads();
        if (kc + 2 < NCHUNK_) LOAD_STAGE((kc + 2) % 3, kc + 2);
        else asm volatile("cp.async.commit_group;" ::: "memory");
        int s = kc % 3;
        uint32_t sA = sb + s * STAGE_;
        uint32_t sB = sA + 18432;
        uint32_t aA = sA + (uint32_t)(wm + (lane & 15)) * RS_ + ((lane >> 4) << 4);
        uint32_t aB = sB + (uint32_t)(wn + (lane & 7) + ((lane & 16) >> 1)) * RS_ + ((lane & 8) << 1);
#pragma unroll
        for (int st = 0; st < 4; st++) {
            uint32_t af[4][4], bfr[2][4];
#pragma unroll
            for (int ta = 0; ta < 4; ta++) ldsm_x4(af[ta], aA + ta * (16 * RS_) + st * 32);
#pragma unroll
            for (int tb = 0; tb < 2; tb++) ldsm_x4(bfr[tb], aB + tb * (16 * RS_) + st * 32);
#pragma unroll
            for (int ta = 0; ta < 4; ta++)
#pragma unroll
                for (int tn = 0; tn < 4; tn++)
                    mma_fp16(acc[ta][tn], af[ta], &bfr[tn >> 1][(tn & 1) * 2]);
        }
    }
#undef LOAD_STAGE

    int g = lane >> 2, tc2 = (lane & 3) * 2;
#pragma unroll
    for (int ta = 0; ta < 4; ta++) {
        int j0 = m0 + wm + ta * 16 + g;
        int j1 = j0 + 8;
#pragma unroll
        for (int tn = 0; tn < 4; tn++) {
            int col = n0 + wn + tn * 8 + tc2;
            float2 lb = *(const float2*)&lin_b[col];
            if (j0 < nrows) {
                float2 o = {acc[ta][tn][0] + lb.x, acc[ta][tn][1] + lb.y};
                *(float2*)&out[(size_t)j0 * V_ + col] = o;
            }
            if (j1 < nrows) {
                float2 o = {acc[ta][tn][2] + lb.x, acc[ta][tn][3] + lb.y};
                *(float2*)&out[(size_t)j1 * V_ + col] = o;
            }
        }
    }
}

// ---------------- launch ----------------
extern "C" void kernel_launch(void* const* d_in, const int* in_sizes, int n_in,
                              void* d_out, int out_size) {
    const float* features = (const float*)d_in[0];
    const int*   captions = (const int*)d_in[1];
    const int*   lengths  = (const int*)d_in[2];
    const float* h0       = (const float*)d_in[3];
    const float* c0       = (const float*)d_in[4];
    const float* embed_w  = (const float*)d_in[5];
    const float* w_ih     = (const float*)d_in[6];
    const float* w_hh     = (const float*)d_in[7];
    const float* b_ih     = (const float*)d_in[8];
    const float* b_hh     = (const float*)d_in[9];
    const float* lin_w    = (const float*)d_in[10];
    const float* lin_b    = (const float*)d_in[11];
    float* out = (float*)d_out;
    int nrows = out_size / V_;

    cudaFuncSetAttribute(out_gemm_mma, cudaFuncAttributeMaxDynamicSharedMemorySize,
                         3 * STAGE_);
    cudaFuncSetAttribute(gx_mma, cudaFuncAttributeMaxDynamicSharedMemorySize,
                         3 * STAGE_);
    cudaFuncSetAttribute(rec_gemm, cudaFuncAttributeMaxDynamicSharedMemorySize,
                         2 * STAGE_);

    // pack indices
    count_kernel<<<T_, 128>>>(lengths);
    offset_kernel<<<1, 1>>>();
    scatter_kernel<<<(T_ * B_ + 255) / 256, 256>>>(lengths);

    // operand builds
    convert_Bout<<<(V_ * 512 / 8) / 256, 256>>>((const float4*)lin_w);
    convert_wih<<<(G4H * 512 / 2) / 256, 256>>>((const float2*)w_ih);
    convert_whh<<<(G4H * 512 / 2) / 256, 256>>>((const float2*)w_hh);
    convert_x2<<<(2560 * 512 / 2) / 256, 256>>>(features, captions, embed_w);
    init_h2<<<(B_ * 512) / 256, 256>>>(h0);

    // input projection (tensor core, fp16 3-term, 3-stage)
    gx_mma<<<dim3(G4H / 128, 2560 / 128), 256, 3 * STAGE_>>>(b_ih, b_hh);

    // recurrence
    for (int t = 0; t < T_; t++) {
        rec_gemm<<<dim3(NSPLIT, G4H / 128), 256, 2 * STAGE_>>>(t);
        cell_reduce<<<(B_ * H_) / 256, 256>>>(t, c0);
    }

    // A operand build (packed-row gather, vectorized)
    convert_Aout<<<(1664 * 512 / 8) / 256, 256>>>();

    // logits GEMM (single fp16, 3-stage)
    int mtiles = (nrows + 127) / 128;   // 13
    out_gemm_mma<<<dim3(V_ / 128, mtiles), 256, 3 * STAGE_>>>(lin_b, out, nrows);
}